// round 10
// baseline (speedup 1.0000x reference)
#include <cuda_runtime.h>
#include <math.h>

#define BB 4
#define NN 4096
#define MM 4096
#define CCH 64
#define KK 32
#define RADIUS 0.1f
#define RAD2 0.01f
#define EPSV 1e-5f

// ---------------- device scratch ----------------
__device__ int      g_idx[BB * NN * KK];
__device__ unsigned g_nbr[BB * NN];
__device__ int      g_idxnn[BB * NN];
__device__ float    g_Wgeff[CCH * CCH];
__device__ float    g_Wqi[CCH * CCH];
__device__ float    g_Wqj[CCH * CCH];
__device__ float    g_bconst[CCH];
__device__ float    g_Qi[BB * MM * CCH];
__device__ float    g_Qj[BB * MM * CCH];
__device__ float    g_AF[BB * MM * CCH];   // includes +b_al fold

// ---------------- warp-bitonic helpers ----------------
__device__ __forceinline__ void bsort32(float& d, int& ix, int lane) {
#pragma unroll
    for (int k = 2; k <= 32; k <<= 1) {
#pragma unroll
        for (int j = k >> 1; j > 0; j >>= 1) {
            float od = __shfl_xor_sync(0xffffffffu, d, j);
            int   oi = __shfl_xor_sync(0xffffffffu, ix, j);
            bool keepMin = (((lane & k) == 0) == ((lane & j) == 0));
            bool take = keepMin ? (od < d) : (od > d);
            if (take) { d = od; ix = oi; }
        }
    }
}
__device__ __forceinline__ void bmerge32(float& d, int& ix, int lane) {
#pragma unroll
    for (int j = 16; j > 0; j >>= 1) {
        float od = __shfl_xor_sync(0xffffffffu, d, j);
        int   oi = __shfl_xor_sync(0xffffffffu, ix, j);
        bool keepMin = ((lane & j) == 0);
        bool take = keepMin ? (od < d) : (od > d);
        if (take) { d = od; ix = oi; }
    }
}

// ---------------- kernel 1: top-K, float4-packed coords + candidate buffer ------
// dyn smem: s4[4096] float4 | bufD[8][64] | bufI[8][64]
constexpr int KNN_SM_FLOATS = 4 * MM + 8 * 64 * 2;   // 17408 floats

__global__ __launch_bounds__(256) void k_knn(const float* __restrict__ qxyz,
                                             const float* __restrict__ sxyz,
                                             const int* __restrict__ smask) {
    extern __shared__ float dsm[];
    float4* s4 = (float4*)dsm;
    int b   = blockIdx.x >> 9;
    int grp = blockIdx.x & 511;
    for (int i = threadIdx.x; i < MM; i += 256) {
        bool v = smask[b * MM + i] > 0;
        float x = sxyz[(b * MM + i) * 3 + 0];
        float y = sxyz[(b * MM + i) * 3 + 1];
        float z = sxyz[(b * MM + i) * 3 + 2];
        float4 val;
        val.x = v ? x : 1e18f;
        val.y = v ? y : 1e18f;
        val.z = v ? z : 1e18f;
        val.w = 0.f;
        s4[i] = val;
    }
    __syncthreads();

    int warp = threadIdx.x >> 5, lane = threadIdx.x & 31;
    float* bD = dsm + 4 * MM + warp * 64;
    int*   bI = (int*)(dsm + 4 * MM + 512) + warp * 64;

    int n  = grp * 8 + warp;
    int qi = b * NN + n;
    float qx = qxyz[qi * 3 + 0];
    float qy = qxyz[qi * 3 + 1];
    float qz = qxyz[qi * 3 + 2];

    float bd = INFINITY; int bi = 0;
    float thr = INFINITY;
    int cnt = 0;
    for (int ch = 0; ch < MM / 32; ++ch) {
        int m = ch * 32 + lane;
        float4 s = s4[m];
        float dx = qx - s.x, dy = qy - s.y, dz = qz - s.z;
        float d2 = fmaf(dx, dx, fmaf(dy, dy, dz * dz));
        bool pass = d2 < thr;
        unsigned mask = __ballot_sync(0xffffffffu, pass);
        if (mask) {
            int pos = cnt + __popc(mask & ((1u << lane) - 1u));
            if (pass) { bD[pos] = d2; bI[pos] = m; }
            cnt += __popc(mask);
            if (cnt >= 32) {
                __syncwarp();
                float nd = bD[lane]; int ni = bI[lane];
                bsort32(nd, ni, lane);
                float rd = __shfl_sync(0xffffffffu, nd, 31 ^ lane);
                int   ri = __shfl_sync(0xffffffffu, ni, 31 ^ lane);
                if (rd < bd) { bd = rd; bi = ri; }
                bmerge32(bd, bi, lane);
                thr = __shfl_sync(0xffffffffu, bd, 31);
                cnt -= 32;
                float sd = 0.f; int si = 0;
                if (lane < cnt) { sd = bD[32 + lane]; si = bI[32 + lane]; }
                __syncwarp();
                if (lane < cnt) { bD[lane] = sd; bI[lane] = si; }
                __syncwarp();
            }
        }
    }
    if (cnt > 0) {
        __syncwarp();
        float nd = (lane < cnt) ? bD[lane] : INFINITY;
        int   ni = (lane < cnt) ? bI[lane] : 0;
        bsort32(nd, ni, lane);
        float rd = __shfl_sync(0xffffffffu, nd, 31 ^ lane);
        int   ri = __shfl_sync(0xffffffffu, ni, 31 ^ lane);
        if (rd < bd) { bd = rd; bi = ri; }
        bmerge32(bd, bi, lane);
    }
    g_idx[qi * KK + lane] = bi;
    unsigned nb = __ballot_sync(0xffffffffu, bd <= RAD2);
    if (lane == 0) { g_nbr[qi] = nb; g_idxnn[qi] = bi; }
}

// ---------------- kernel 2: compose weight matrices ----------------
__global__ __launch_bounds__(256) void k_compose(
    const float* __restrict__ Wg1, const float* __restrict__ Wg2,
    const float* __restrict__ Wphi, const float* __restrict__ Wpsi,
    const float* __restrict__ bphi, const float* __restrict__ bpsi,
    const float* __restrict__ bg1, const float* __restrict__ bg2) {
    __shared__ float G[CCH * CCH];
    int tid = threadIdx.x;
    for (int e = tid; e < 4096; e += 256) {
        int o = e >> 6, i = e & 63;
        float a = 0.f;
        for (int c = 0; c < 64; ++c)
            a = fmaf(Wg2[o * 64 + c], Wg1[c * 64 + i], a);
        G[e] = a;
        g_Wgeff[e] = a;
    }
    __syncthreads();
    for (int e = tid; e < 4096; e += 256) {
        int o = e >> 6, i = e & 63;
        float qi = 0.f, qj = 0.f;
        for (int c = 0; c < 64; ++c) {
            float g = G[o * 64 + c];
            qi = fmaf(g, Wphi[c * 64 + i], qi);
            qj = fmaf(g, Wpsi[c * 64 + i], qj);
        }
        g_Wqi[e] = qi;
        g_Wqj[e] = qj;
    }
    if (tid < 64) {
        float a = bg2[tid];
        for (int c = 0; c < 64; ++c)
            a = fmaf(Wg2[tid * 64 + c], bg1[c], a);
        for (int i = 0; i < 64; ++i)
            a = fmaf(G[tid * 64 + i], bphi[i] - bpsi[i], a);
        g_bconst[tid] = a;
    }
}

// ---------------- kernel 3: per-support precompute (bal folded into AF) --------
#define STRD 36
constexpr int PRE_WQI = 0, PRE_WQJ = 4096, PRE_WAL = 8192, PRE_X = 12288;
constexpr int PRE_SM = PRE_X + 64 * STRD;

__global__ __launch_bounds__(256) void k_pre(const float* __restrict__ feat,
                                             const float* __restrict__ Wal,
                                             const float* __restrict__ bal) {
    extern __shared__ float s[];
    int tid = threadIdx.x;
    for (int e = tid; e < 4096; e += 256) {
        int o = e >> 6, in = e & 63;
        s[PRE_WQI + in * 64 + o] = g_Wqi[e];
        s[PRE_WQJ + in * 64 + o] = g_Wqj[e];
        s[PRE_WAL + in * 64 + o] = Wal[e];
    }

    int base = blockIdx.x * 32;
    int b    = base >> 12;
    int m0   = base & (MM - 1);
    int c = tid & 63, g = tid >> 6, k0 = g * 8;
    float* xS = s + PRE_X;
    for (int i = tid; i < 2048; i += 256) {
        int k = i & 31, cc = i >> 5;
        xS[cc * STRD + k] = feat[((long)b * CCH + cc) * MM + m0 + k];
    }
    __syncthreads();

    float balc = bal[c];
    float qi[8], qj[8], af[8];
#pragma unroll
    for (int kk = 0; kk < 8; ++kk) { qi[kk] = 0.f; qj[kk] = 0.f; af[kk] = 0.f; }
    const float* Wi = s + PRE_WQI + c;
    const float* Wj = s + PRE_WQJ + c;
    const float* Wa = s + PRE_WAL + c;
    const float* xb = xS + k0;
#pragma unroll 4
    for (int c2 = 0; c2 < 64; ++c2) {
        float wi = Wi[c2 * 64], wj = Wj[c2 * 64], wa = Wa[c2 * 64];
        float4 x0 = *(const float4*)(xb + c2 * STRD);
        float4 x1 = *(const float4*)(xb + c2 * STRD + 4);
        qi[0] = fmaf(wi, x0.x, qi[0]); qi[1] = fmaf(wi, x0.y, qi[1]);
        qi[2] = fmaf(wi, x0.z, qi[2]); qi[3] = fmaf(wi, x0.w, qi[3]);
        qi[4] = fmaf(wi, x1.x, qi[4]); qi[5] = fmaf(wi, x1.y, qi[5]);
        qi[6] = fmaf(wi, x1.z, qi[6]); qi[7] = fmaf(wi, x1.w, qi[7]);
        qj[0] = fmaf(wj, x0.x, qj[0]); qj[1] = fmaf(wj, x0.y, qj[1]);
        qj[2] = fmaf(wj, x0.z, qj[2]); qj[3] = fmaf(wj, x0.w, qj[3]);
        qj[4] = fmaf(wj, x1.x, qj[4]); qj[5] = fmaf(wj, x1.y, qj[5]);
        qj[6] = fmaf(wj, x1.z, qj[6]); qj[7] = fmaf(wj, x1.w, qj[7]);
        af[0] = fmaf(wa, x0.x, af[0]); af[1] = fmaf(wa, x0.y, af[1]);
        af[2] = fmaf(wa, x0.z, af[2]); af[3] = fmaf(wa, x0.w, af[3]);
        af[4] = fmaf(wa, x1.x, af[4]); af[5] = fmaf(wa, x1.y, af[5]);
        af[6] = fmaf(wa, x1.z, af[6]); af[7] = fmaf(wa, x1.w, af[7]);
    }
#pragma unroll
    for (int kk = 0; kk < 8; ++kk) {
        long o = (long)(base + k0 + kk) * 64 + c;
        g_Qi[o] = qi[kk];
        g_Qj[o] = qj[kk];
        g_AF[o] = af[kk] + balc;
    }
}

// ---------------- kernel 4: fused per-query (128 thr, dual-query shared-W) -----
struct P2 {
    const float *qxyz, *sxyz;
    const int   *qmask;
    const float *Wth1, *bth1, *Wth2, *bth2;
    const float *gt, *bet, *rmt, *rvt, *gg, *beg, *rmg, *rvg;
    float* out;
};

constexpr int OFF_WG   = 0;       // WgT[c2][c] 4096
constexpr int OFF_WEFF = 4096;    // 64*4 theta-fold
constexpr int OFF_CC   = 4352;    // bconst(64)
constexpr int OFF_BN   = 4416;    // 4*64
constexpr int OFF_Q    = 4672;
// per-query: dl [64*36] | pos [32*4] | fm [32] | kidx [32]
constexpr int QO_DL = 0, QO_POS = 2304, QO_FM = 2432, QO_KIDX = 2464;
constexpr int QSZ = 2496;
constexpr int SMEM_FLOATS = OFF_Q + 2 * QSZ;   // 9664 floats = 38656 B

__global__ __launch_bounds__(128, 4) void k_main(P2 p) {
    extern __shared__ float sm[];
    int tid = threadIdx.x;

    // ---- init (128 threads) ----
    {
        for (int i = tid; i < 4096; i += 128) {
            int o = i >> 6, in = i & 63;
            sm[OFF_WG + in * 64 + o] = g_Wgeff[i];
        }
        for (int i = tid; i < 256; i += 128) {
            int cc = i >> 2, j = i & 3;
            float acc;
            if (j < 3) {
                acc = 0.f;
                for (int c2 = 0; c2 < 64; ++c2)
                    acc = fmaf(p.Wth2[cc * 64 + c2], p.Wth1[c2 * 3 + j], acc);
            } else {
                acc = p.bth2[cc];
                for (int c2 = 0; c2 < 64; ++c2)
                    acc = fmaf(p.Wth2[cc * 64 + c2], p.bth1[c2], acc);
            }
            sm[OFF_WEFF + cc * 4 + j] = acc;
        }
        if (tid < 64) {
            int i = tid;
            sm[OFF_CC + i] = g_bconst[i];
            float it = p.gt[i] * rsqrtf(p.rvt[i] + EPSV);
            sm[OFF_BN + 0 * 64 + i] = it;
            sm[OFF_BN + 1 * 64 + i] = p.bet[i] - p.rmt[i] * it;
            float ig = p.gg[i] * rsqrtf(p.rvg[i] + EPSV);
            sm[OFF_BN + 2 * 64 + i] = ig;
            sm[OFF_BN + 3 * 64 + i] = p.beg[i] - p.rmg[i] * ig;
        }
    }
    __syncthreads();

    int g  = tid & 7;             // k-group (lane bits 0-2)
    int cp = tid >> 3;            // channel quad 0..15
    int c0 = cp * 4;
    int k0 = g * 4;

    float* Q0 = sm + OFF_Q;
    float* Q1 = sm + OFF_Q + QSZ;

    const int ngrp = (BB * NN) / 2;
    for (int grp = blockIdx.x; grp < ngrp; grp += gridDim.x) {
        int b  = (grp * 2) >> 12;
        long rowbase = (long)b * MM;

        // ---- setup: threads 0-31 -> q0, threads 32-63 -> q1 ----
        if (tid < 64) {
            int qq = tid >> 5;
            int k  = tid & 31;
            int qi = grp * 2 + qq;
            float* Q = qq ? Q1 : Q0;
            int ki = g_idx[qi * KK + k];
            ((int*)(Q + QO_KIDX))[k] = ki;
            float qx = p.qxyz[qi * 3 + 0];
            float qy = p.qxyz[qi * 3 + 1];
            float qz = p.qxyz[qi * 3 + 2];
            const float* s = p.sxyz + (rowbase + ki) * 3;
            float4 pp;
            pp.x = (s[0] - qx) * (1.0f / RADIUS);
            pp.y = (s[1] - qy) * (1.0f / RADIUS);
            pp.z = (s[2] - qz) * (1.0f / RADIUS);
            pp.w = 0.f;
            *(float4*)(Q + QO_POS + k * 4) = pp;
            unsigned nb = g_nbr[qi];
            int qm = p.qmask[qi];
            (Q + QO_FM)[k] = (float)((nb >> k) & 1u) + (1.0f - (float)qm);
        }
        __syncthreads();   // S1

        // ---- delta for BOTH queries, (c0..c0+3) x (k0..k0+3) ----
        float4 rowA[4], rowB[4];
        {
            float4 invt4 = *(const float4*)(sm + OFF_BN + 0 * 64 + c0);
            float4 sht4  = *(const float4*)(sm + OFF_BN + 1 * 64 + c0);
#pragma unroll
            for (int kk = 0; kk < 4; ++kk) {
                float4 pA = *(const float4*)(Q0 + QO_POS + (k0 + kk) * 4);
                float4 pB = *(const float4*)(Q1 + QO_POS + (k0 + kk) * 4);
#pragma unroll
                for (int j = 0; j < 4; ++j) {
                    float4 wej = *(const float4*)(sm + OFF_WEFF + (c0 + j) * 4);
                    float dA = wej.w, dB = wej.w;
                    dA = fmaf(wej.x, pA.x, dA); dB = fmaf(wej.x, pB.x, dB);
                    dA = fmaf(wej.y, pA.y, dA); dB = fmaf(wej.y, pB.y, dB);
                    dA = fmaf(wej.z, pA.z, dA); dB = fmaf(wej.z, pB.z, dB);
                    (&rowA[j].x)[kk] = fmaxf(fmaf(dA, (&invt4.x)[j], (&sht4.x)[j]), 0.f);
                    (&rowB[j].x)[kk] = fmaxf(fmaf(dB, (&invt4.x)[j], (&sht4.x)[j]), 0.f);
                }
            }
#pragma unroll
            for (int j = 0; j < 4; ++j) {
                *(float4*)(Q0 + QO_DL + (c0 + j) * STRD + k0) = rowA[j];
                *(float4*)(Q1 + QO_DL + (c0 + j) * STRD + k0) = rowB[j];
            }
        }
        __syncthreads();   // S2

        // ---- matvec for BOTH queries: one weight load serves 32 FMAs ----
        float accA[16], accB[16];
#pragma unroll
        for (int i = 0; i < 16; ++i) { accA[i] = 0.f; accB[i] = 0.f; }
        {
            const float* W  = sm + OFF_WG + c0;
            const float* dA = Q0 + QO_DL + k0;
            const float* dB = Q1 + QO_DL + k0;
#pragma unroll 4
            for (int c2 = 0; c2 < 64; ++c2) {
                float4 w4 = *(const float4*)(W + c2 * 64);
                float4 a4 = *(const float4*)(dA + c2 * STRD);
                float4 b4 = *(const float4*)(dB + c2 * STRD);
#pragma unroll
                for (int j = 0; j < 4; ++j) {
                    float w = (&w4.x)[j];
                    accA[j * 4 + 0] = fmaf(w, a4.x, accA[j * 4 + 0]);
                    accA[j * 4 + 1] = fmaf(w, a4.y, accA[j * 4 + 1]);
                    accA[j * 4 + 2] = fmaf(w, a4.z, accA[j * 4 + 2]);
                    accA[j * 4 + 3] = fmaf(w, a4.w, accA[j * 4 + 3]);
                    accB[j * 4 + 0] = fmaf(w, b4.x, accB[j * 4 + 0]);
                    accB[j * 4 + 1] = fmaf(w, b4.y, accB[j * 4 + 1]);
                    accB[j * 4 + 2] = fmaf(w, b4.z, accB[j * 4 + 2]);
                    accB[j * 4 + 3] = fmaf(w, b4.w, accB[j * 4 + 3]);
                }
            }
        }

        // ---- epilogue per query ----
        float4 bcn4  = *(const float4*)(sm + OFF_CC + c0);
        float4 invg4 = *(const float4*)(sm + OFF_BN + 2 * 64 + c0);
        float4 shg4  = *(const float4*)(sm + OFF_BN + 3 * 64 + c0);
#pragma unroll
        for (int qq = 0; qq < 2; ++qq) {
            int qi = grp * 2 + qq;
            int n  = qi & (NN - 1);
            float* Q = qq ? Q1 : Q0;
            float* acc = qq ? accB : accA;
            float4* rowp = qq ? rowB : rowA;
            int* kidx = (int*)(Q + QO_KIDX);
            float* fmB = Q + QO_FM;

            int nn = g_idxnn[qi];
            float4 qi4 = *(const float4*)(g_Qi + (rowbase + nn) * 64 + c0);
            float se[4] = {0.f, 0.f, 0.f, 0.f};
            float sf[4] = {0.f, 0.f, 0.f, 0.f};
#pragma unroll
            for (int kk = 0; kk < 4; ++kk) {
                int k = k0 + kk;
                int ridx = kidx[k];
                float4 qj4 = *(const float4*)(g_Qj + (rowbase + ridx) * 64 + c0);
                float4 af4 = *(const float4*)(g_AF + (rowbase + ridx) * 64 + c0);
                float fm = fmB[k];
#pragma unroll
                for (int j = 0; j < 4; ++j) {
                    float pre2 = (&qi4.x)[j] - (&qj4.x)[j] + acc[j * 4 + kk] + (&bcn4.x)[j];
                    float v = fmaxf(fmaf(pre2, (&invg4.x)[j], (&shg4.x)[j]), 0.f);
                    float e = __expf(v);
                    float ftv = ((&af4.x)[j] + (&rowp[j].x)[kk]) * fm;
                    se[j] += e;
                    sf[j] = fmaf(e, ftv, sf[j]);
                }
            }
#pragma unroll
            for (int j = 0; j < 4; ++j) {
                float s1 = se[j], s2 = sf[j];
                s1 += __shfl_xor_sync(0xffffffffu, s1, 1);
                s2 += __shfl_xor_sync(0xffffffffu, s2, 1);
                s1 += __shfl_xor_sync(0xffffffffu, s1, 2);
                s2 += __shfl_xor_sync(0xffffffffu, s2, 2);
                s1 += __shfl_xor_sync(0xffffffffu, s1, 4);
                s2 += __shfl_xor_sync(0xffffffffu, s2, 4);
                if (g == 0)
                    p.out[((long)b * CCH + c0 + j) * NN + n] = s2 / s1;
            }
        }
        __syncthreads();   // S3
    }
}

// ---------------- host launcher ----------------
extern "C" void kernel_launch(void* const* d_in, const int* in_sizes, int n_in,
                              void* d_out, int out_size) {
    const float* qxyz  = (const float*)d_in[0];
    const float* sxyz  = (const float*)d_in[1];
    const int*   qmask = (const int*)d_in[2];
    const int*   smask = (const int*)d_in[3];
    const float* feat  = (const float*)d_in[4];
    const float* Wth1  = (const float*)d_in[5];
    const float* bth1  = (const float*)d_in[6];
    const float* Wth2  = (const float*)d_in[7];
    const float* bth2  = (const float*)d_in[8];
    const float* Wphi  = (const float*)d_in[9];
    const float* bphi  = (const float*)d_in[10];
    const float* Wpsi  = (const float*)d_in[11];
    const float* bpsi  = (const float*)d_in[12];
    const float* Wal   = (const float*)d_in[13];
    const float* bal   = (const float*)d_in[14];
    const float* Wg1   = (const float*)d_in[15];
    const float* bg1   = (const float*)d_in[16];
    const float* Wg2   = (const float*)d_in[17];
    const float* bg2   = (const float*)d_in[18];

    P2 p;
    p.qxyz = qxyz; p.sxyz = sxyz; p.qmask = qmask;
    p.Wth1 = Wth1; p.bth1 = bth1; p.Wth2 = Wth2; p.bth2 = bth2;
    p.gt   = (const float*)d_in[19]; p.bet  = (const float*)d_in[20];
    p.rmt  = (const float*)d_in[21]; p.rvt  = (const float*)d_in[22];
    p.gg   = (const float*)d_in[23]; p.beg  = (const float*)d_in[24];
    p.rmg  = (const float*)d_in[25]; p.rvg  = (const float*)d_in[26];
    p.out  = (float*)d_out;

    k_compose<<<1, 256>>>(Wg1, Wg2, Wphi, Wpsi, bphi, bpsi, bg1, bg2);

    cudaFuncSetAttribute(k_knn, cudaFuncAttributeMaxDynamicSharedMemorySize,
                         KNN_SM_FLOATS * 4);
    k_knn<<<(BB * NN) / 8, 256, KNN_SM_FLOATS * 4>>>(qxyz, sxyz, smask);

    cudaFuncSetAttribute(k_pre, cudaFuncAttributeMaxDynamicSharedMemorySize,
                         PRE_SM * 4);
    k_pre<<<(BB * MM) / 32, 256, PRE_SM * 4>>>(feat, Wal, bal);

    cudaFuncSetAttribute(k_main, cudaFuncAttributeMaxDynamicSharedMemorySize,
                         SMEM_FLOATS * 4);
    int dev = 0, nsm = 148;
    cudaGetDevice(&dev);
    cudaDeviceGetAttribute(&nsm, cudaDevAttrMultiProcessorCount, dev);
    k_main<<<4 * nsm, 128, SMEM_FLOATS * 4>>>(p);
}

// round 11
// speedup vs baseline: 1.0534x; 1.0534x over previous
#include <cuda_runtime.h>
#include <math.h>

#define BB 4
#define NN 4096
#define MM 4096
#define CCH 64
#define KK 32
#define RADIUS 0.1f
#define RAD2 0.01f
#define EPSV 1e-5f

// ---------------- device scratch ----------------
__device__ int      g_idx[BB * NN * KK];
__device__ unsigned g_nbr[BB * NN];
__device__ int      g_idxnn[BB * NN];
__device__ float    g_Wgeff[CCH * CCH];
__device__ float    g_Wqi[CCH * CCH];
__device__ float    g_Wqj[CCH * CCH];
__device__ float    g_bconst[CCH];
__device__ float    g_Qi[BB * MM * CCH];
__device__ float    g_Qj[BB * MM * CCH];
__device__ float    g_AF[BB * MM * CCH];   // includes +b_al fold

// ---------------- warp-bitonic helpers ----------------
__device__ __forceinline__ void bsort32(float& d, int& ix, int lane) {
#pragma unroll
    for (int k = 2; k <= 32; k <<= 1) {
#pragma unroll
        for (int j = k >> 1; j > 0; j >>= 1) {
            float od = __shfl_xor_sync(0xffffffffu, d, j);
            int   oi = __shfl_xor_sync(0xffffffffu, ix, j);
            bool keepMin = (((lane & k) == 0) == ((lane & j) == 0));
            bool take = keepMin ? (od < d) : (od > d);
            if (take) { d = od; ix = oi; }
        }
    }
}
__device__ __forceinline__ void bmerge32(float& d, int& ix, int lane) {
#pragma unroll
    for (int j = 16; j > 0; j >>= 1) {
        float od = __shfl_xor_sync(0xffffffffu, d, j);
        int   oi = __shfl_xor_sync(0xffffffffu, ix, j);
        bool keepMin = ((lane & j) == 0);
        bool take = keepMin ? (od < d) : (od > d);
        if (take) { d = od; ix = oi; }
    }
}

// ---------------- kernel 1: top-K (R9 scalar-arrays version, proven) ----------
constexpr int KNN_SM_FLOATS = 3 * MM + 8 * 64 * 2;   // 13312 floats

__global__ __launch_bounds__(256) void k_knn(const float* __restrict__ qxyz,
                                             const float* __restrict__ sxyz,
                                             const int* __restrict__ smask) {
    extern __shared__ float dsm[];
    float* sx = dsm;
    float* sy = dsm + MM;
    float* sz = dsm + 2 * MM;
    int b   = blockIdx.x >> 9;
    int grp = blockIdx.x & 511;
    for (int i = threadIdx.x; i < MM; i += 256) {
        bool v = smask[b * MM + i] > 0;
        float x = sxyz[(b * MM + i) * 3 + 0];
        float y = sxyz[(b * MM + i) * 3 + 1];
        float z = sxyz[(b * MM + i) * 3 + 2];
        sx[i] = v ? x : 1e18f;
        sy[i] = v ? y : 1e18f;
        sz[i] = v ? z : 1e18f;
    }
    __syncthreads();

    int warp = threadIdx.x >> 5, lane = threadIdx.x & 31;
    float* bD = dsm + 3 * MM + warp * 64;
    int*   bI = (int*)(dsm + 3 * MM + 512) + warp * 64;

    int n  = grp * 8 + warp;
    int qi = b * NN + n;
    float qx = qxyz[qi * 3 + 0];
    float qy = qxyz[qi * 3 + 1];
    float qz = qxyz[qi * 3 + 2];

    float bd = INFINITY; int bi = 0;
    float thr = INFINITY;
    int cnt = 0;
    for (int ch = 0; ch < MM / 32; ++ch) {
        int m = ch * 32 + lane;
        float dx = qx - sx[m], dy = qy - sy[m], dz = qz - sz[m];
        float d2 = fmaf(dx, dx, fmaf(dy, dy, dz * dz));
        bool pass = d2 < thr;
        unsigned mask = __ballot_sync(0xffffffffu, pass);
        if (mask) {
            int pos = cnt + __popc(mask & ((1u << lane) - 1u));
            if (pass) { bD[pos] = d2; bI[pos] = m; }
            cnt += __popc(mask);
            if (cnt >= 32) {
                __syncwarp();
                float nd = bD[lane]; int ni = bI[lane];
                bsort32(nd, ni, lane);
                float rd = __shfl_sync(0xffffffffu, nd, 31 ^ lane);
                int   ri = __shfl_sync(0xffffffffu, ni, 31 ^ lane);
                if (rd < bd) { bd = rd; bi = ri; }
                bmerge32(bd, bi, lane);
                thr = __shfl_sync(0xffffffffu, bd, 31);
                cnt -= 32;
                float sd = 0.f; int si = 0;
                if (lane < cnt) { sd = bD[32 + lane]; si = bI[32 + lane]; }
                __syncwarp();
                if (lane < cnt) { bD[lane] = sd; bI[lane] = si; }
                __syncwarp();
            }
        }
    }
    if (cnt > 0) {
        __syncwarp();
        float nd = (lane < cnt) ? bD[lane] : INFINITY;
        int   ni = (lane < cnt) ? bI[lane] : 0;
        bsort32(nd, ni, lane);
        float rd = __shfl_sync(0xffffffffu, nd, 31 ^ lane);
        int   ri = __shfl_sync(0xffffffffu, ni, 31 ^ lane);
        if (rd < bd) { bd = rd; bi = ri; }
        bmerge32(bd, bi, lane);
    }
    g_idx[qi * KK + lane] = bi;
    unsigned nb = __ballot_sync(0xffffffffu, bd <= RAD2);
    if (lane == 0) { g_nbr[qi] = nb; g_idxnn[qi] = bi; }
}

// ---------------- kernel 2: compose weight matrices ----------------
__global__ __launch_bounds__(256) void k_compose(
    const float* __restrict__ Wg1, const float* __restrict__ Wg2,
    const float* __restrict__ Wphi, const float* __restrict__ Wpsi,
    const float* __restrict__ bphi, const float* __restrict__ bpsi,
    const float* __restrict__ bg1, const float* __restrict__ bg2) {
    __shared__ float G[CCH * CCH];
    int tid = threadIdx.x;
    for (int e = tid; e < 4096; e += 256) {
        int o = e >> 6, i = e & 63;
        float a = 0.f;
        for (int c = 0; c < 64; ++c)
            a = fmaf(Wg2[o * 64 + c], Wg1[c * 64 + i], a);
        G[e] = a;
        g_Wgeff[e] = a;
    }
    __syncthreads();
    for (int e = tid; e < 4096; e += 256) {
        int o = e >> 6, i = e & 63;
        float qi = 0.f, qj = 0.f;
        for (int c = 0; c < 64; ++c) {
            float g = G[o * 64 + c];
            qi = fmaf(g, Wphi[c * 64 + i], qi);
            qj = fmaf(g, Wpsi[c * 64 + i], qj);
        }
        g_Wqi[e] = qi;
        g_Wqj[e] = qj;
    }
    if (tid < 64) {
        float a = bg2[tid];
        for (int c = 0; c < 64; ++c)
            a = fmaf(Wg2[tid * 64 + c], bg1[c], a);
        for (int i = 0; i < 64; ++i)
            a = fmaf(G[tid * 64 + i], bphi[i] - bpsi[i], a);
        g_bconst[tid] = a;
    }
}

// ---------------- kernel 3: per-support precompute (bal folded into AF) --------
#define STRD 36
constexpr int PRE_WQI = 0, PRE_WQJ = 4096, PRE_WAL = 8192, PRE_X = 12288;
constexpr int PRE_SM = PRE_X + 64 * STRD;

__global__ __launch_bounds__(256) void k_pre(const float* __restrict__ feat,
                                             const float* __restrict__ Wal,
                                             const float* __restrict__ bal) {
    extern __shared__ float s[];
    int tid = threadIdx.x;
    for (int e = tid; e < 4096; e += 256) {
        int o = e >> 6, in = e & 63;
        s[PRE_WQI + in * 64 + o] = g_Wqi[e];
        s[PRE_WQJ + in * 64 + o] = g_Wqj[e];
        s[PRE_WAL + in * 64 + o] = Wal[e];
    }

    int base = blockIdx.x * 32;
    int b    = base >> 12;
    int m0   = base & (MM - 1);
    int c = tid & 63, g = tid >> 6, k0 = g * 8;
    float* xS = s + PRE_X;
    for (int i = tid; i < 2048; i += 256) {
        int k = i & 31, cc = i >> 5;
        xS[cc * STRD + k] = feat[((long)b * CCH + cc) * MM + m0 + k];
    }
    __syncthreads();

    float balc = bal[c];
    float qi[8], qj[8], af[8];
#pragma unroll
    for (int kk = 0; kk < 8; ++kk) { qi[kk] = 0.f; qj[kk] = 0.f; af[kk] = 0.f; }
    const float* Wi = s + PRE_WQI + c;
    const float* Wj = s + PRE_WQJ + c;
    const float* Wa = s + PRE_WAL + c;
    const float* xb = xS + k0;
#pragma unroll 4
    for (int c2 = 0; c2 < 64; ++c2) {
        float wi = Wi[c2 * 64], wj = Wj[c2 * 64], wa = Wa[c2 * 64];
        float4 x0 = *(const float4*)(xb + c2 * STRD);
        float4 x1 = *(const float4*)(xb + c2 * STRD + 4);
        qi[0] = fmaf(wi, x0.x, qi[0]); qi[1] = fmaf(wi, x0.y, qi[1]);
        qi[2] = fmaf(wi, x0.z, qi[2]); qi[3] = fmaf(wi, x0.w, qi[3]);
        qi[4] = fmaf(wi, x1.x, qi[4]); qi[5] = fmaf(wi, x1.y, qi[5]);
        qi[6] = fmaf(wi, x1.z, qi[6]); qi[7] = fmaf(wi, x1.w, qi[7]);
        qj[0] = fmaf(wj, x0.x, qj[0]); qj[1] = fmaf(wj, x0.y, qj[1]);
        qj[2] = fmaf(wj, x0.z, qj[2]); qj[3] = fmaf(wj, x0.w, qj[3]);
        qj[4] = fmaf(wj, x1.x, qj[4]); qj[5] = fmaf(wj, x1.y, qj[5]);
        qj[6] = fmaf(wj, x1.z, qj[6]); qj[7] = fmaf(wj, x1.w, qj[7]);
        af[0] = fmaf(wa, x0.x, af[0]); af[1] = fmaf(wa, x0.y, af[1]);
        af[2] = fmaf(wa, x0.z, af[2]); af[3] = fmaf(wa, x0.w, af[3]);
        af[4] = fmaf(wa, x1.x, af[4]); af[5] = fmaf(wa, x1.y, af[5]);
        af[6] = fmaf(wa, x1.z, af[6]); af[7] = fmaf(wa, x1.w, af[7]);
    }
#pragma unroll
    for (int kk = 0; kk < 8; ++kk) {
        long o = (long)(base + k0 + kk) * 64 + c;
        g_Qi[o] = qi[kk];
        g_Qj[o] = qj[kk];
        g_AF[o] = af[kk] + balc;
    }
}

// ---------------- kernel 4: fused per-query (8c x 4k dual-query tiles) ---------
struct P2 {
    const float *qxyz, *sxyz;
    const int   *qmask;
    const float *Wth1, *bth1, *Wth2, *bth2;
    const float *gt, *bet, *rmt, *rvt, *gg, *beg, *rmg, *rvg;
    float* out;
};

constexpr int OFF_WG   = 0;       // WgT[c2][c] 4096
constexpr int OFF_WEFF = 4096;    // 64*4 theta-fold
constexpr int OFF_CC   = 4352;    // bconst(64)
constexpr int OFF_BN   = 4416;    // 4*64
constexpr int OFF_Q    = 4672;
// per-query: dl [64*36] | pos [32*4] | fm [32] | kidx [32]
constexpr int QO_DL = 0, QO_POS = 2304, QO_FM = 2432, QO_KIDX = 2464;
constexpr int QSZ = 2496;
constexpr int SMEM_FLOATS = OFF_Q + 4 * QSZ;   // 14656 floats = 58624 B

__global__ __launch_bounds__(128, 2) void k_main(P2 p) {
    extern __shared__ float sm[];
    int tid = threadIdx.x;

    // ---- init (128 threads) ----
    {
        for (int i = tid; i < 4096; i += 128) {
            int o = i >> 6, in = i & 63;
            sm[OFF_WG + in * 64 + o] = g_Wgeff[i];
        }
        for (int i = tid; i < 256; i += 128) {
            int cc = i >> 2, j = i & 3;
            float acc;
            if (j < 3) {
                acc = 0.f;
                for (int c2 = 0; c2 < 64; ++c2)
                    acc = fmaf(p.Wth2[cc * 64 + c2], p.Wth1[c2 * 3 + j], acc);
            } else {
                acc = p.bth2[cc];
                for (int c2 = 0; c2 < 64; ++c2)
                    acc = fmaf(p.Wth2[cc * 64 + c2], p.bth1[c2], acc);
            }
            sm[OFF_WEFF + cc * 4 + j] = acc;
        }
        if (tid < 64) {
            int i = tid;
            sm[OFF_CC + i] = g_bconst[i];
            float it = p.gt[i] * rsqrtf(p.rvt[i] + EPSV);
            sm[OFF_BN + 0 * 64 + i] = it;
            sm[OFF_BN + 1 * 64 + i] = p.bet[i] - p.rmt[i] * it;
            float ig = p.gg[i] * rsqrtf(p.rvg[i] + EPSV);
            sm[OFF_BN + 2 * 64 + i] = ig;
            sm[OFF_BN + 3 * 64 + i] = p.beg[i] - p.rmg[i] * ig;
        }
    }
    __syncthreads();

    int pr = tid >> 6;            // pair in CTA (0..1)
    int t  = tid & 63;
    int g  = t & 7;               // k-group (lane bits 0-2)
    int cq = t >> 3;              // channel oct 0..7
    int c0 = cq * 8;
    int k0 = g * 4;

    float* QA = sm + OFF_Q + (pr * 2 + 0) * QSZ;
    float* QB = sm + OFF_Q + (pr * 2 + 1) * QSZ;

    const int ngrp = (BB * NN) / 4;     // 4 queries per CTA iteration
    for (int grp = blockIdx.x; grp < ngrp; grp += gridDim.x) {
        int b  = (grp * 4) >> 12;
        long rowbase = (long)b * MM;

        // ---- setup: thread (tid>>5) handles query (0..3), k = tid&31 ----
        {
            int qq = tid >> 5;
            int k  = tid & 31;
            int qi = grp * 4 + qq;
            float* Q = sm + OFF_Q + qq * QSZ;
            int ki = g_idx[qi * KK + k];
            ((int*)(Q + QO_KIDX))[k] = ki;
            float qx = p.qxyz[qi * 3 + 0];
            float qy = p.qxyz[qi * 3 + 1];
            float qz = p.qxyz[qi * 3 + 2];
            const float* s = p.sxyz + (rowbase + ki) * 3;
            float4 pp;
            pp.x = (s[0] - qx) * (1.0f / RADIUS);
            pp.y = (s[1] - qy) * (1.0f / RADIUS);
            pp.z = (s[2] - qz) * (1.0f / RADIUS);
            pp.w = 0.f;
            *(float4*)(Q + QO_POS + k * 4) = pp;
            unsigned nb = g_nbr[qi];
            int qm = p.qmask[qi];
            (Q + QO_FM)[k] = (float)((nb >> k) & 1u) + (1.0f - (float)qm);
        }
        __syncthreads();   // S1

        // ---- delta for BOTH pair queries, 8 channels x 4 k ----
        {
            float4 invtL = *(const float4*)(sm + OFF_BN + 0 * 64 + c0);
            float4 invtH = *(const float4*)(sm + OFF_BN + 0 * 64 + c0 + 4);
            float4 shtL  = *(const float4*)(sm + OFF_BN + 1 * 64 + c0);
            float4 shtH  = *(const float4*)(sm + OFF_BN + 1 * 64 + c0 + 4);
            float4 pA[4], pB[4];
#pragma unroll
            for (int kk = 0; kk < 4; ++kk) {
                pA[kk] = *(const float4*)(QA + QO_POS + (k0 + kk) * 4);
                pB[kk] = *(const float4*)(QB + QO_POS + (k0 + kk) * 4);
            }
#pragma unroll
            for (int j = 0; j < 8; ++j) {
                float4 wej = *(const float4*)(sm + OFF_WEFF + (c0 + j) * 4);
                float it = (j < 4) ? (&invtL.x)[j] : (&invtH.x)[j - 4];
                float sh = (j < 4) ? (&shtL.x)[j] : (&shtH.x)[j - 4];
                float4 rA, rB;
#pragma unroll
                for (int kk = 0; kk < 4; ++kk) {
                    float dA = wej.w, dB = wej.w;
                    dA = fmaf(wej.x, pA[kk].x, dA); dB = fmaf(wej.x, pB[kk].x, dB);
                    dA = fmaf(wej.y, pA[kk].y, dA); dB = fmaf(wej.y, pB[kk].y, dB);
                    dA = fmaf(wej.z, pA[kk].z, dA); dB = fmaf(wej.z, pB[kk].z, dB);
                    (&rA.x)[kk] = fmaxf(fmaf(dA, it, sh), 0.f);
                    (&rB.x)[kk] = fmaxf(fmaf(dB, it, sh), 0.f);
                }
                *(float4*)(QA + QO_DL + (c0 + j) * STRD + k0) = rA;
                *(float4*)(QB + QO_DL + (c0 + j) * STRD + k0) = rB;
            }
        }
        __syncthreads();   // S2

        // ---- matvec: 8c x 4k for BOTH queries; 4 LDS per 64 FMA ----
        float accA[32], accB[32];
#pragma unroll
        for (int i = 0; i < 32; ++i) { accA[i] = 0.f; accB[i] = 0.f; }
        {
            const float* W  = sm + OFF_WG + c0;
            const float* dA = QA + QO_DL + k0;
            const float* dB = QB + QO_DL + k0;
#pragma unroll 2
            for (int c2 = 0; c2 < 64; ++c2) {
                float4 w0 = *(const float4*)(W + c2 * 64);
                float4 w1 = *(const float4*)(W + c2 * 64 + 4);
                float4 a4 = *(const float4*)(dA + c2 * STRD);
                float4 b4 = *(const float4*)(dB + c2 * STRD);
#pragma unroll
                for (int j = 0; j < 8; ++j) {
                    float w = (j < 4) ? (&w0.x)[j] : (&w1.x)[j - 4];
                    accA[j * 4 + 0] = fmaf(w, a4.x, accA[j * 4 + 0]);
                    accA[j * 4 + 1] = fmaf(w, a4.y, accA[j * 4 + 1]);
                    accA[j * 4 + 2] = fmaf(w, a4.z, accA[j * 4 + 2]);
                    accA[j * 4 + 3] = fmaf(w, a4.w, accA[j * 4 + 3]);
                    accB[j * 4 + 0] = fmaf(w, b4.x, accB[j * 4 + 0]);
                    accB[j * 4 + 1] = fmaf(w, b4.y, accB[j * 4 + 1]);
                    accB[j * 4 + 2] = fmaf(w, b4.z, accB[j * 4 + 2]);
                    accB[j * 4 + 3] = fmaf(w, b4.w, accB[j * 4 + 3]);
                }
            }
        }

        // ---- epilogue per query of the pair ----
        float4 bcnL  = *(const float4*)(sm + OFF_CC + c0);
        float4 bcnH  = *(const float4*)(sm + OFF_CC + c0 + 4);
        float4 invgL = *(const float4*)(sm + OFF_BN + 2 * 64 + c0);
        float4 invgH = *(const float4*)(sm + OFF_BN + 2 * 64 + c0 + 4);
        float4 shgL  = *(const float4*)(sm + OFF_BN + 3 * 64 + c0);
        float4 shgH  = *(const float4*)(sm + OFF_BN + 3 * 64 + c0 + 4);
#pragma unroll
        for (int qq = 0; qq < 2; ++qq) {
            int qi = grp * 4 + pr * 2 + qq;
            int n  = qi & (NN - 1);
            float* Q = qq ? QB : QA;
            float* acc = qq ? accB : accA;
            int* kidx = (int*)(Q + QO_KIDX);
            float* fmB = Q + QO_FM;

            // re-read own delta rows (8 x float4)
            float4 dl4[8];
#pragma unroll
            for (int j = 0; j < 8; ++j)
                dl4[j] = *(const float4*)(Q + QO_DL + (c0 + j) * STRD + k0);

            int nn = g_idxnn[qi];
            float4 qiL = *(const float4*)(g_Qi + (rowbase + nn) * 64 + c0);
            float4 qiH = *(const float4*)(g_Qi + (rowbase + nn) * 64 + c0 + 4);
            float se[8] = {0.f, 0.f, 0.f, 0.f, 0.f, 0.f, 0.f, 0.f};
            float sf[8] = {0.f, 0.f, 0.f, 0.f, 0.f, 0.f, 0.f, 0.f};
#pragma unroll
            for (int kk = 0; kk < 4; ++kk) {
                int k = k0 + kk;
                int ridx = kidx[k];
                float4 qjL = *(const float4*)(g_Qj + (rowbase + ridx) * 64 + c0);
                float4 qjH = *(const float4*)(g_Qj + (rowbase + ridx) * 64 + c0 + 4);
                float4 afL = *(const float4*)(g_AF + (rowbase + ridx) * 64 + c0);
                float4 afH = *(const float4*)(g_AF + (rowbase + ridx) * 64 + c0 + 4);
                float fm = fmB[k];
#pragma unroll
                for (int j = 0; j < 8; ++j) {
                    float qiv = (j < 4) ? (&qiL.x)[j] : (&qiH.x)[j - 4];
                    float qjv = (j < 4) ? (&qjL.x)[j] : (&qjH.x)[j - 4];
                    float afv = (j < 4) ? (&afL.x)[j] : (&afH.x)[j - 4];
                    float bc  = (j < 4) ? (&bcnL.x)[j] : (&bcnH.x)[j - 4];
                    float ig  = (j < 4) ? (&invgL.x)[j] : (&invgH.x)[j - 4];
                    float sg  = (j < 4) ? (&shgL.x)[j] : (&shgH.x)[j - 4];
                    float pre2 = qiv - qjv + acc[j * 4 + kk] + bc;
                    float v = fmaxf(fmaf(pre2, ig, sg), 0.f);
                    float e = __expf(v);
                    float ftv = (afv + (&dl4[j].x)[kk]) * fm;
                    se[j] += e;
                    sf[j] = fmaf(e, ftv, sf[j]);
                }
            }
#pragma unroll
            for (int j = 0; j < 8; ++j) {
                float s1 = se[j], s2 = sf[j];
                s1 += __shfl_xor_sync(0xffffffffu, s1, 1);
                s2 += __shfl_xor_sync(0xffffffffu, s2, 1);
                s1 += __shfl_xor_sync(0xffffffffu, s1, 2);
                s2 += __shfl_xor_sync(0xffffffffu, s2, 2);
                s1 += __shfl_xor_sync(0xffffffffu, s1, 4);
                s2 += __shfl_xor_sync(0xffffffffu, s2, 4);
                if (g == 0)
                    p.out[((long)b * CCH + c0 + j) * NN + n] = s2 / s1;
            }
        }
        __syncthreads();   // S3
    }
}

// ---------------- host launcher ----------------
extern "C" void kernel_launch(void* const* d_in, const int* in_sizes, int n_in,
                              void* d_out, int out_size) {
    const float* qxyz  = (const float*)d_in[0];
    const float* sxyz  = (const float*)d_in[1];
    const int*   qmask = (const int*)d_in[2];
    const int*   smask = (const int*)d_in[3];
    const float* feat  = (const float*)d_in[4];
    const float* Wth1  = (const float*)d_in[5];
    const float* bth1  = (const float*)d_in[6];
    const float* Wth2  = (const float*)d_in[7];
    const float* bth2  = (const float*)d_in[8];
    const float* Wphi  = (const float*)d_in[9];
    const float* bphi  = (const float*)d_in[10];
    const float* Wpsi  = (const float*)d_in[11];
    const float* bpsi  = (const float*)d_in[12];
    const float* Wal   = (const float*)d_in[13];
    const float* bal   = (const float*)d_in[14];
    const float* Wg1   = (const float*)d_in[15];
    const float* bg1   = (const float*)d_in[16];
    const float* Wg2   = (const float*)d_in[17];
    const float* bg2   = (const float*)d_in[18];

    P2 p;
    p.qxyz = qxyz; p.sxyz = sxyz; p.qmask = qmask;
    p.Wth1 = Wth1; p.bth1 = bth1; p.Wth2 = Wth2; p.bth2 = bth2;
    p.gt   = (const float*)d_in[19]; p.bet  = (const float*)d_in[20];
    p.rmt  = (const float*)d_in[21]; p.rvt  = (const float*)d_in[22];
    p.gg   = (const float*)d_in[23]; p.beg  = (const float*)d_in[24];
    p.rmg  = (const float*)d_in[25]; p.rvg  = (const float*)d_in[26];
    p.out  = (float*)d_out;

    k_compose<<<1, 256>>>(Wg1, Wg2, Wphi, Wpsi, bphi, bpsi, bg1, bg2);

    cudaFuncSetAttribute(k_knn, cudaFuncAttributeMaxDynamicSharedMemorySize,
                         KNN_SM_FLOATS * 4);
    k_knn<<<(BB * NN) / 8, 256, KNN_SM_FLOATS * 4>>>(qxyz, sxyz, smask);

    cudaFuncSetAttribute(k_pre, cudaFuncAttributeMaxDynamicSharedMemorySize,
                         PRE_SM * 4);
    k_pre<<<(BB * MM) / 32, 256, PRE_SM * 4>>>(feat, Wal, bal);

    cudaFuncSetAttribute(k_main, cudaFuncAttributeMaxDynamicSharedMemorySize,
                         SMEM_FLOATS * 4);
    int dev = 0, nsm = 148;
    cudaGetDevice(&dev);
    cudaDeviceGetAttribute(&nsm, cudaDevAttrMultiProcessorCount, dev);
    k_main<<<2 * nsm, 128, SMEM_FLOATS * 4>>>(p);
}

// round 12
// speedup vs baseline: 1.2373x; 1.1746x over previous
#include <cuda_runtime.h>
#include <math.h>

#define BB 4
#define NN 4096
#define MM 4096
#define CCH 64
#define KK 32
#define RADIUS 0.1f
#define RAD2 0.01f
#define EPSV 1e-5f

// ---------------- device scratch ----------------
__device__ int      g_idx[BB * NN * KK];
__device__ unsigned g_nbr[BB * NN];
__device__ int      g_idxnn[BB * NN];
__device__ float    g_Wgeff[CCH * CCH];   // row-major [o][i]  (k_main)
__device__ float    g_WqiT[CCH * CCH];    // transposed [i][o] (k_pre)
__device__ float    g_WqjT[CCH * CCH];    // transposed [i][o]
__device__ float    g_WalT[CCH * CCH];    // transposed [i][o]
__device__ float    g_bconst[CCH];
__device__ float    g_Qi[BB * MM * CCH];
__device__ float    g_Qj[BB * MM * CCH];
__device__ float    g_AF[BB * MM * CCH];  // includes +b_al fold

// ---------------- warp-bitonic helpers ----------------
__device__ __forceinline__ void bsort32(float& d, int& ix, int lane) {
#pragma unroll
    for (int k = 2; k <= 32; k <<= 1) {
#pragma unroll
        for (int j = k >> 1; j > 0; j >>= 1) {
            float od = __shfl_xor_sync(0xffffffffu, d, j);
            int   oi = __shfl_xor_sync(0xffffffffu, ix, j);
            bool keepMin = (((lane & k) == 0) == ((lane & j) == 0));
            bool take = keepMin ? (od < d) : (od > d);
            if (take) { d = od; ix = oi; }
        }
    }
}
__device__ __forceinline__ void bmerge32(float& d, int& ix, int lane) {
#pragma unroll
    for (int j = 16; j > 0; j >>= 1) {
        float od = __shfl_xor_sync(0xffffffffu, d, j);
        int   oi = __shfl_xor_sync(0xffffffffu, ix, j);
        bool keepMin = ((lane & j) == 0);
        bool take = keepMin ? (od < d) : (od > d);
        if (take) { d = od; ix = oi; }
    }
}

// ---------------- kernel 1: top-K (R9 scalar-arrays version, proven) ----------
constexpr int KNN_SM_FLOATS = 3 * MM + 8 * 64 * 2;   // 13312 floats

__global__ __launch_bounds__(256) void k_knn(const float* __restrict__ qxyz,
                                             const float* __restrict__ sxyz,
                                             const int* __restrict__ smask) {
    extern __shared__ float dsm[];
    float* sx = dsm;
    float* sy = dsm + MM;
    float* sz = dsm + 2 * MM;
    int b   = blockIdx.x >> 9;
    int grp = blockIdx.x & 511;
    for (int i = threadIdx.x; i < MM; i += 256) {
        bool v = smask[b * MM + i] > 0;
        float x = sxyz[(b * MM + i) * 3 + 0];
        float y = sxyz[(b * MM + i) * 3 + 1];
        float z = sxyz[(b * MM + i) * 3 + 2];
        sx[i] = v ? x : 1e18f;
        sy[i] = v ? y : 1e18f;
        sz[i] = v ? z : 1e18f;
    }
    __syncthreads();

    int warp = threadIdx.x >> 5, lane = threadIdx.x & 31;
    float* bD = dsm + 3 * MM + warp * 64;
    int*   bI = (int*)(dsm + 3 * MM + 512) + warp * 64;

    int n  = grp * 8 + warp;
    int qi = b * NN + n;
    float qx = qxyz[qi * 3 + 0];
    float qy = qxyz[qi * 3 + 1];
    float qz = qxyz[qi * 3 + 2];

    float bd = INFINITY; int bi = 0;
    float thr = INFINITY;
    int cnt = 0;
    for (int ch = 0; ch < MM / 32; ++ch) {
        int m = ch * 32 + lane;
        float dx = qx - sx[m], dy = qy - sy[m], dz = qz - sz[m];
        float d2 = fmaf(dx, dx, fmaf(dy, dy, dz * dz));
        bool pass = d2 < thr;
        unsigned mask = __ballot_sync(0xffffffffu, pass);
        if (mask) {
            int pos = cnt + __popc(mask & ((1u << lane) - 1u));
            if (pass) { bD[pos] = d2; bI[pos] = m; }
            cnt += __popc(mask);
            if (cnt >= 32) {
                __syncwarp();
                float nd = bD[lane]; int ni = bI[lane];
                bsort32(nd, ni, lane);
                float rd = __shfl_sync(0xffffffffu, nd, 31 ^ lane);
                int   ri = __shfl_sync(0xffffffffu, ni, 31 ^ lane);
                if (rd < bd) { bd = rd; bi = ri; }
                bmerge32(bd, bi, lane);
                thr = __shfl_sync(0xffffffffu, bd, 31);
                cnt -= 32;
                float sd = 0.f; int si = 0;
                if (lane < cnt) { sd = bD[32 + lane]; si = bI[32 + lane]; }
                __syncwarp();
                if (lane < cnt) { bD[lane] = sd; bI[lane] = si; }
                __syncwarp();
            }
        }
    }
    if (cnt > 0) {
        __syncwarp();
        float nd = (lane < cnt) ? bD[lane] : INFINITY;
        int   ni = (lane < cnt) ? bI[lane] : 0;
        bsort32(nd, ni, lane);
        float rd = __shfl_sync(0xffffffffu, nd, 31 ^ lane);
        int   ri = __shfl_sync(0xffffffffu, ni, 31 ^ lane);
        if (rd < bd) { bd = rd; bi = ri; }
        bmerge32(bd, bi, lane);
    }
    g_idx[qi * KK + lane] = bi;
    unsigned nb = __ballot_sync(0xffffffffu, bd <= RAD2);
    if (lane == 0) { g_nbr[qi] = nb; g_idxnn[qi] = bi; }
}

// ---------------- kernel 2a: Wgeff = Wg2@Wg1; WalT transpose ----------------
__global__ void k_compose1(const float* __restrict__ Wg1,
                           const float* __restrict__ Wg2,
                           const float* __restrict__ Wal) {
    int e = blockIdx.x * 256 + threadIdx.x;   // 0..4095
    int o = e >> 6, i = e & 63;
    float a = 0.f;
    for (int c = 0; c < 64; ++c)
        a = fmaf(Wg2[o * 64 + c], Wg1[c * 64 + i], a);
    g_Wgeff[e] = a;
    g_WalT[i * 64 + o] = Wal[e];
}

// ---------------- kernel 2b: WqiT/WqjT = (Wgeff@Wphi/psi)^T; bconst ----------
__global__ void k_compose2(const float* __restrict__ Wphi,
                           const float* __restrict__ Wpsi,
                           const float* __restrict__ bphi,
                           const float* __restrict__ bpsi,
                           const float* __restrict__ bg1,
                           const float* __restrict__ bg2,
                           const float* __restrict__ Wg2) {
    int e = blockIdx.x * 256 + threadIdx.x;
    int o = e >> 6, i = e & 63;
    float qi = 0.f, qj = 0.f;
    for (int c = 0; c < 64; ++c) {
        float g = g_Wgeff[o * 64 + c];
        qi = fmaf(g, Wphi[c * 64 + i], qi);
        qj = fmaf(g, Wpsi[c * 64 + i], qj);
    }
    g_WqiT[i * 64 + o] = qi;
    g_WqjT[i * 64 + o] = qj;
    if (e < 64) {
        float a = bg2[e];
        for (int c = 0; c < 64; ++c)
            a = fmaf(Wg2[e * 64 + c], bg1[c], a);
        for (int j = 0; j < 64; ++j)
            a = fmaf(g_Wgeff[e * 64 + j], bphi[j] - bpsi[j], a);
        g_bconst[e] = a;
    }
}

// ---------------- kernel 3: per-support precompute (4c x 8k tiles) ------------
#define STRD 36
constexpr int PRE_WQI = 0, PRE_WQJ = 4096, PRE_WAL = 8192, PRE_X = 12288;
constexpr int PRE_SM = PRE_X + 64 * STRD;   // 14592 floats = 58368 B

__global__ __launch_bounds__(64) void k_pre(const float* __restrict__ feat,
                                            const float* __restrict__ bal) {
    extern __shared__ float s[];
    int tid = threadIdx.x;

    // straight coalesced copy (weights already transposed by compose)
    for (int i = tid; i < 4096; i += 64) {
        s[PRE_WQI + i] = g_WqiT[i];
        s[PRE_WQJ + i] = g_WqjT[i];
        s[PRE_WAL + i] = g_WalT[i];
    }

    int base = blockIdx.x * 32;               // 512 blocks
    int b    = base >> 12;
    int m0   = base & (MM - 1);
    float* xS = s + PRE_X;
    for (int i = tid; i < 2048; i += 64) {
        int k = i & 31, cc = i >> 5;
        xS[cc * STRD + k] = feat[((long)b * CCH + cc) * MM + m0 + k];
    }
    __syncthreads();

    int cq = tid >> 2;            // 0..15
    int g  = tid & 3;             // 0..3
    int c0 = cq * 4;
    int k0 = g * 8;

    float4 aqi[8], aqj[8], aaf[8];
#pragma unroll
    for (int kk = 0; kk < 8; ++kk) {
        aqi[kk] = make_float4(0.f, 0.f, 0.f, 0.f);
        aqj[kk] = make_float4(0.f, 0.f, 0.f, 0.f);
        aaf[kk] = make_float4(0.f, 0.f, 0.f, 0.f);
    }
    {
        const float* Wi = s + PRE_WQI + c0;
        const float* Wj = s + PRE_WQJ + c0;
        const float* Wa = s + PRE_WAL + c0;
        const float* xb = xS + k0;
#pragma unroll 4
        for (int c2 = 0; c2 < 64; ++c2) {
            float4 wi4 = *(const float4*)(Wi + c2 * 64);
            float4 wj4 = *(const float4*)(Wj + c2 * 64);
            float4 wa4 = *(const float4*)(Wa + c2 * 64);
            float4 x0 = *(const float4*)(xb + c2 * STRD);
            float4 x1 = *(const float4*)(xb + c2 * STRD + 4);
#pragma unroll
            for (int kk = 0; kk < 8; ++kk) {
                float xv = (kk < 4) ? (&x0.x)[kk] : (&x1.x)[kk - 4];
                aqi[kk].x = fmaf(wi4.x, xv, aqi[kk].x);
                aqi[kk].y = fmaf(wi4.y, xv, aqi[kk].y);
                aqi[kk].z = fmaf(wi4.z, xv, aqi[kk].z);
                aqi[kk].w = fmaf(wi4.w, xv, aqi[kk].w);
                aqj[kk].x = fmaf(wj4.x, xv, aqj[kk].x);
                aqj[kk].y = fmaf(wj4.y, xv, aqj[kk].y);
                aqj[kk].z = fmaf(wj4.z, xv, aqj[kk].z);
                aqj[kk].w = fmaf(wj4.w, xv, aqj[kk].w);
                aaf[kk].x = fmaf(wa4.x, xv, aaf[kk].x);
                aaf[kk].y = fmaf(wa4.y, xv, aaf[kk].y);
                aaf[kk].z = fmaf(wa4.z, xv, aaf[kk].z);
                aaf[kk].w = fmaf(wa4.w, xv, aaf[kk].w);
            }
        }
    }
    float4 balv = *(const float4*)(bal + c0);
#pragma unroll
    for (int kk = 0; kk < 8; ++kk) {
        long o = (long)(base + k0 + kk) * 64 + c0;
        *(float4*)(g_Qi + o) = aqi[kk];
        *(float4*)(g_Qj + o) = aqj[kk];
        float4 af = aaf[kk];
        af.x += balv.x; af.y += balv.y; af.z += balv.z; af.w += balv.w;
        *(float4*)(g_AF + o) = af;
    }
}

// ---------------- kernel 4: fused per-query (8c x 4k dual-query tiles) ---------
struct P2 {
    const float *qxyz, *sxyz;
    const int   *qmask;
    const float *Wth1, *bth1, *Wth2, *bth2;
    const float *gt, *bet, *rmt, *rvt, *gg, *beg, *rmg, *rvg;
    float* out;
};

constexpr int OFF_WG   = 0;       // WgT[c2][c] 4096
constexpr int OFF_WEFF = 4096;    // 64*4 theta-fold
constexpr int OFF_CC   = 4352;    // bconst(64)
constexpr int OFF_BN   = 4416;    // 4*64
constexpr int OFF_Q    = 4672;
constexpr int QO_DL = 0, QO_POS = 2304, QO_FM = 2432, QO_KIDX = 2464;
constexpr int QSZ = 2496;
constexpr int SMEM_FLOATS = OFF_Q + 4 * QSZ;   // 14656 floats = 58624 B

__global__ __launch_bounds__(128, 2) void k_main(P2 p) {
    extern __shared__ float sm[];
    int tid = threadIdx.x;

    {
        for (int i = tid; i < 4096; i += 128) {
            int o = i >> 6, in = i & 63;
            sm[OFF_WG + in * 64 + o] = g_Wgeff[i];
        }
        for (int i = tid; i < 256; i += 128) {
            int cc = i >> 2, j = i & 3;
            float acc;
            if (j < 3) {
                acc = 0.f;
                for (int c2 = 0; c2 < 64; ++c2)
                    acc = fmaf(p.Wth2[cc * 64 + c2], p.Wth1[c2 * 3 + j], acc);
            } else {
                acc = p.bth2[cc];
                for (int c2 = 0; c2 < 64; ++c2)
                    acc = fmaf(p.Wth2[cc * 64 + c2], p.bth1[c2], acc);
            }
            sm[OFF_WEFF + cc * 4 + j] = acc;
        }
        if (tid < 64) {
            int i = tid;
            sm[OFF_CC + i] = g_bconst[i];
            float it = p.gt[i] * rsqrtf(p.rvt[i] + EPSV);
            sm[OFF_BN + 0 * 64 + i] = it;
            sm[OFF_BN + 1 * 64 + i] = p.bet[i] - p.rmt[i] * it;
            float ig = p.gg[i] * rsqrtf(p.rvg[i] + EPSV);
            sm[OFF_BN + 2 * 64 + i] = ig;
            sm[OFF_BN + 3 * 64 + i] = p.beg[i] - p.rmg[i] * ig;
        }
    }
    __syncthreads();

    int pr = tid >> 6;
    int t  = tid & 63;
    int g  = t & 7;
    int cq = t >> 3;
    int c0 = cq * 8;
    int k0 = g * 4;

    float* QA = sm + OFF_Q + (pr * 2 + 0) * QSZ;
    float* QB = sm + OFF_Q + (pr * 2 + 1) * QSZ;

    const int ngrp = (BB * NN) / 4;
    for (int grp = blockIdx.x; grp < ngrp; grp += gridDim.x) {
        int b  = (grp * 4) >> 12;
        long rowbase = (long)b * MM;

        {
            int qq = tid >> 5;
            int k  = tid & 31;
            int qi = grp * 4 + qq;
            float* Q = sm + OFF_Q + qq * QSZ;
            int ki = g_idx[qi * KK + k];
            ((int*)(Q + QO_KIDX))[k] = ki;
            float qx = p.qxyz[qi * 3 + 0];
            float qy = p.qxyz[qi * 3 + 1];
            float qz = p.qxyz[qi * 3 + 2];
            const float* s = p.sxyz + (rowbase + ki) * 3;
            float4 pp;
            pp.x = (s[0] - qx) * (1.0f / RADIUS);
            pp.y = (s[1] - qy) * (1.0f / RADIUS);
            pp.z = (s[2] - qz) * (1.0f / RADIUS);
            pp.w = 0.f;
            *(float4*)(Q + QO_POS + k * 4) = pp;
            unsigned nb = g_nbr[qi];
            int qm = p.qmask[qi];
            (Q + QO_FM)[k] = (float)((nb >> k) & 1u) + (1.0f - (float)qm);
        }
        __syncthreads();   // S1

        {
            float4 invtL = *(const float4*)(sm + OFF_BN + 0 * 64 + c0);
            float4 invtH = *(const float4*)(sm + OFF_BN + 0 * 64 + c0 + 4);
            float4 shtL  = *(const float4*)(sm + OFF_BN + 1 * 64 + c0);
            float4 shtH  = *(const float4*)(sm + OFF_BN + 1 * 64 + c0 + 4);
            float4 pA[4], pB[4];
#pragma unroll
            for (int kk = 0; kk < 4; ++kk) {
                pA[kk] = *(const float4*)(QA + QO_POS + (k0 + kk) * 4);
                pB[kk] = *(const float4*)(QB + QO_POS + (k0 + kk) * 4);
            }
#pragma unroll
            for (int j = 0; j < 8; ++j) {
                float4 wej = *(const float4*)(sm + OFF_WEFF + (c0 + j) * 4);
                float it = (j < 4) ? (&invtL.x)[j] : (&invtH.x)[j - 4];
                float sh = (j < 4) ? (&shtL.x)[j] : (&shtH.x)[j - 4];
                float4 rA, rB;
#pragma unroll
                for (int kk = 0; kk < 4; ++kk) {
                    float dA = wej.w, dB = wej.w;
                    dA = fmaf(wej.x, pA[kk].x, dA); dB = fmaf(wej.x, pB[kk].x, dB);
                    dA = fmaf(wej.y, pA[kk].y, dA); dB = fmaf(wej.y, pB[kk].y, dB);
                    dA = fmaf(wej.z, pA[kk].z, dA); dB = fmaf(wej.z, pB[kk].z, dB);
                    (&rA.x)[kk] = fmaxf(fmaf(dA, it, sh), 0.f);
                    (&rB.x)[kk] = fmaxf(fmaf(dB, it, sh), 0.f);
                }
                *(float4*)(QA + QO_DL + (c0 + j) * STRD + k0) = rA;
                *(float4*)(QB + QO_DL + (c0 + j) * STRD + k0) = rB;
            }
        }
        __syncthreads();   // S2

        float accA[32], accB[32];
#pragma unroll
        for (int i = 0; i < 32; ++i) { accA[i] = 0.f; accB[i] = 0.f; }
        {
            const float* W  = sm + OFF_WG + c0;
            const float* dA = QA + QO_DL + k0;
            const float* dB = QB + QO_DL + k0;
#pragma unroll 2
            for (int c2 = 0; c2 < 64; ++c2) {
                float4 w0 = *(const float4*)(W + c2 * 64);
                float4 w1 = *(const float4*)(W + c2 * 64 + 4);
                float4 a4 = *(const float4*)(dA + c2 * STRD);
                float4 b4 = *(const float4*)(dB + c2 * STRD);
#pragma unroll
                for (int j = 0; j < 8; ++j) {
                    float w = (j < 4) ? (&w0.x)[j] : (&w1.x)[j - 4];
                    accA[j * 4 + 0] = fmaf(w, a4.x, accA[j * 4 + 0]);
                    accA[j * 4 + 1] = fmaf(w, a4.y, accA[j * 4 + 1]);
                    accA[j * 4 + 2] = fmaf(w, a4.z, accA[j * 4 + 2]);
                    accA[j * 4 + 3] = fmaf(w, a4.w, accA[j * 4 + 3]);
                    accB[j * 4 + 0] = fmaf(w, b4.x, accB[j * 4 + 0]);
                    accB[j * 4 + 1] = fmaf(w, b4.y, accB[j * 4 + 1]);
                    accB[j * 4 + 2] = fmaf(w, b4.z, accB[j * 4 + 2]);
                    accB[j * 4 + 3] = fmaf(w, b4.w, accB[j * 4 + 3]);
                }
            }
        }

        float4 bcnL  = *(const float4*)(sm + OFF_CC + c0);
        float4 bcnH  = *(const float4*)(sm + OFF_CC + c0 + 4);
        float4 invgL = *(const float4*)(sm + OFF_BN + 2 * 64 + c0);
        float4 invgH = *(const float4*)(sm + OFF_BN + 2 * 64 + c0 + 4);
        float4 shgL  = *(const float4*)(sm + OFF_BN + 3 * 64 + c0);
        float4 shgH  = *(const float4*)(sm + OFF_BN + 3 * 64 + c0 + 4);
#pragma unroll
        for (int qq = 0; qq < 2; ++qq) {
            int qi = grp * 4 + pr * 2 + qq;
            int n  = qi & (NN - 1);
            float* Q = qq ? QB : QA;
            float* acc = qq ? accB : accA;
            int* kidx = (int*)(Q + QO_KIDX);
            float* fmB = Q + QO_FM;

            float4 dl4[8];
#pragma unroll
            for (int j = 0; j < 8; ++j)
                dl4[j] = *(const float4*)(Q + QO_DL + (c0 + j) * STRD + k0);

            int nn = g_idxnn[qi];
            float4 qiL = *(const float4*)(g_Qi + (rowbase + nn) * 64 + c0);
            float4 qiH = *(const float4*)(g_Qi + (rowbase + nn) * 64 + c0 + 4);
            float se[8] = {0.f, 0.f, 0.f, 0.f, 0.f, 0.f, 0.f, 0.f};
            float sf[8] = {0.f, 0.f, 0.f, 0.f, 0.f, 0.f, 0.f, 0.f};
#pragma unroll
            for (int kk = 0; kk < 4; ++kk) {
                int k = k0 + kk;
                int ridx = kidx[k];
                float4 qjL = *(const float4*)(g_Qj + (rowbase + ridx) * 64 + c0);
                float4 qjH = *(const float4*)(g_Qj + (rowbase + ridx) * 64 + c0 + 4);
                float4 afL = *(const float4*)(g_AF + (rowbase + ridx) * 64 + c0);
                float4 afH = *(const float4*)(g_AF + (rowbase + ridx) * 64 + c0 + 4);
                float fm = fmB[k];
#pragma unroll
                for (int j = 0; j < 8; ++j) {
                    float qiv = (j < 4) ? (&qiL.x)[j] : (&qiH.x)[j - 4];
                    float qjv = (j < 4) ? (&qjL.x)[j] : (&qjH.x)[j - 4];
                    float afv = (j < 4) ? (&afL.x)[j] : (&afH.x)[j - 4];
                    float bc  = (j < 4) ? (&bcnL.x)[j] : (&bcnH.x)[j - 4];
                    float ig  = (j < 4) ? (&invgL.x)[j] : (&invgH.x)[j - 4];
                    float sg  = (j < 4) ? (&shgL.x)[j] : (&shgH.x)[j - 4];
                    float pre2 = qiv - qjv + acc[j * 4 + kk] + bc;
                    float v = fmaxf(fmaf(pre2, ig, sg), 0.f);
                    float e = __expf(v);
                    float ftv = (afv + (&dl4[j].x)[kk]) * fm;
                    se[j] += e;
                    sf[j] = fmaf(e, ftv, sf[j]);
                }
            }
#pragma unroll
            for (int j = 0; j < 8; ++j) {
                float s1 = se[j], s2 = sf[j];
                s1 += __shfl_xor_sync(0xffffffffu, s1, 1);
                s2 += __shfl_xor_sync(0xffffffffu, s2, 1);
                s1 += __shfl_xor_sync(0xffffffffu, s1, 2);
                s2 += __shfl_xor_sync(0xffffffffu, s2, 2);
                s1 += __shfl_xor_sync(0xffffffffu, s1, 4);
                s2 += __shfl_xor_sync(0xffffffffu, s2, 4);
                if (g == 0)
                    p.out[((long)b * CCH + c0 + j) * NN + n] = s2 / s1;
            }
        }
        __syncthreads();   // S3
    }
}

// ---------------- host launcher ----------------
extern "C" void kernel_launch(void* const* d_in, const int* in_sizes, int n_in,
                              void* d_out, int out_size) {
    const float* qxyz  = (const float*)d_in[0];
    const float* sxyz  = (const float*)d_in[1];
    const int*   qmask = (const int*)d_in[2];
    const int*   smask = (const int*)d_in[3];
    const float* feat  = (const float*)d_in[4];
    const float* Wth1  = (const float*)d_in[5];
    const float* bth1  = (const float*)d_in[6];
    const float* Wth2  = (const float*)d_in[7];
    const float* bth2  = (const float*)d_in[8];
    const float* Wphi  = (const float*)d_in[9];
    const float* bphi  = (const float*)d_in[10];
    const float* Wpsi  = (const float*)d_in[11];
    const float* bpsi  = (const float*)d_in[12];
    const float* Wal   = (const float*)d_in[13];
    const float* bal   = (const float*)d_in[14];
    const float* Wg1   = (const float*)d_in[15];
    const float* bg1   = (const float*)d_in[16];
    const float* Wg2   = (const float*)d_in[17];
    const float* bg2   = (const float*)d_in[18];

    P2 p;
    p.qxyz = qxyz; p.sxyz = sxyz; p.qmask = qmask;
    p.Wth1 = Wth1; p.bth1 = bth1; p.Wth2 = Wth2; p.bth2 = bth2;
    p.gt   = (const float*)d_in[19]; p.bet  = (const float*)d_in[20];
    p.rmt  = (const float*)d_in[21]; p.rvt  = (const float*)d_in[22];
    p.gg   = (const float*)d_in[23]; p.beg  = (const float*)d_in[24];
    p.rmg  = (const float*)d_in[25]; p.rvg  = (const float*)d_in[26];
    p.out  = (float*)d_out;

    k_compose1<<<16, 256>>>(Wg1, Wg2, Wal);
    k_compose2<<<16, 256>>>(Wphi, Wpsi, bphi, bpsi, bg1, bg2, Wg2);

    cudaFuncSetAttribute(k_knn, cudaFuncAttributeMaxDynamicSharedMemorySize,
                         KNN_SM_FLOATS * 4);
    k_knn<<<(BB * NN) / 8, 256, KNN_SM_FLOATS * 4>>>(qxyz, sxyz, smask);

    cudaFuncSetAttribute(k_pre, cudaFuncAttributeMaxDynamicSharedMemorySize,
                         PRE_SM * 4);
    k_pre<<<(BB * MM) / 32, 64, PRE_SM * 4>>>(feat, bal);

    cudaFuncSetAttribute(k_main, cudaFuncAttributeMaxDynamicSharedMemorySize,
                         SMEM_FLOATS * 4);
    int dev = 0, nsm = 148;
    cudaGetDevice(&dev);
    cudaDeviceGetAttribute(&nsm, cudaDevAttrMultiProcessorCount, dev);
    k_main<<<2 * nsm, 128, SMEM_FLOATS * 4>>>(p);
}

// round 13
// speedup vs baseline: 1.3128x; 1.0610x over previous
#include <cuda_runtime.h>
#include <math.h>

#define BB 4
#define NN 4096
#define MM 4096
#define CCH 64
#define KK 32
#define RADIUS 0.1f
#define RAD2 0.01f
#define EPSV 1e-5f

// ---------------- device scratch ----------------
__device__ int      g_idx[BB * NN * KK];
__device__ unsigned g_nbr[BB * NN];
__device__ int      g_idxnn[BB * NN];
__device__ float    g_Wgeff[CCH * CCH];   // row-major [o][i]  (k_main)
__device__ float    g_WqiT[CCH * CCH];    // transposed [i][o] (k_pre)
__device__ float    g_WqjT[CCH * CCH];    // transposed [i][o]
__device__ float    g_WalT[CCH * CCH];    // transposed [i][o]
__device__ float    g_bconst[CCH];
__device__ float    g_Qi[BB * MM * CCH];
__device__ float    g_Qj[BB * MM * CCH];
__device__ float    g_AF[BB * MM * CCH];  // includes +b_al fold

// ---------------- warp-bitonic helpers ----------------
__device__ __forceinline__ void bsort32(float& d, int& ix, int lane) {
#pragma unroll
    for (int k = 2; k <= 32; k <<= 1) {
#pragma unroll
        for (int j = k >> 1; j > 0; j >>= 1) {
            float od = __shfl_xor_sync(0xffffffffu, d, j);
            int   oi = __shfl_xor_sync(0xffffffffu, ix, j);
            bool keepMin = (((lane & k) == 0) == ((lane & j) == 0));
            bool take = keepMin ? (od < d) : (od > d);
            if (take) { d = od; ix = oi; }
        }
    }
}
__device__ __forceinline__ void bmerge32(float& d, int& ix, int lane) {
#pragma unroll
    for (int j = 16; j > 0; j >>= 1) {
        float od = __shfl_xor_sync(0xffffffffu, d, j);
        int   oi = __shfl_xor_sync(0xffffffffu, ix, j);
        bool keepMin = ((lane & j) == 0);
        bool take = keepMin ? (od < d) : (od > d);
        if (take) { d = od; ix = oi; }
    }
}

__device__ __forceinline__ void knn_flush(float* bD, int* bI, float& bd, int& bi,
                                          float& thr, int& cnt, int lane) {
    __syncwarp();
    float nd = bD[lane]; int ni = bI[lane];
    bsort32(nd, ni, lane);
    float rd = __shfl_sync(0xffffffffu, nd, 31 ^ lane);
    int   ri = __shfl_sync(0xffffffffu, ni, 31 ^ lane);
    if (rd < bd) { bd = rd; bi = ri; }
    bmerge32(bd, bi, lane);
    thr = __shfl_sync(0xffffffffu, bd, 31);
    cnt -= 32;
    float sd = 0.f; int si = 0;
    if (lane < cnt) { sd = bD[32 + lane]; si = bI[32 + lane]; }
    __syncwarp();
    if (lane < cnt) { bD[lane] = sd; bI[lane] = si; }
    __syncwarp();
}

// ---------------- kernel 1: top-K, 2 queries per warp ----------------
// dyn smem: sx/sy/sz [4096 each] | bufD [16][64] | bufI [16][64]
constexpr int KNN_SM_FLOATS = 3 * MM + 16 * 64 * 2;   // 14336 floats = 57344 B

__global__ __launch_bounds__(256) void k_knn(const float* __restrict__ qxyz,
                                             const float* __restrict__ sxyz,
                                             const int* __restrict__ smask) {
    extern __shared__ float dsm[];
    float* sx = dsm;
    float* sy = dsm + MM;
    float* sz = dsm + 2 * MM;
    int b   = blockIdx.x >> 8;        // 256 blocks per batch, 16 queries/block
    int grp = blockIdx.x & 255;
    for (int i = threadIdx.x; i < MM; i += 256) {
        bool v = smask[b * MM + i] > 0;
        float x = sxyz[(b * MM + i) * 3 + 0];
        float y = sxyz[(b * MM + i) * 3 + 1];
        float z = sxyz[(b * MM + i) * 3 + 2];
        sx[i] = v ? x : 1e18f;
        sy[i] = v ? y : 1e18f;
        sz[i] = v ? z : 1e18f;
    }
    __syncthreads();

    int warp = threadIdx.x >> 5, lane = threadIdx.x & 31;
    float* bD0 = dsm + 3 * MM + (warp * 2 + 0) * 64;
    float* bD1 = dsm + 3 * MM + (warp * 2 + 1) * 64;
    int*   bI0 = (int*)(dsm + 3 * MM + 1024) + (warp * 2 + 0) * 64;
    int*   bI1 = (int*)(dsm + 3 * MM + 1024) + (warp * 2 + 1) * 64;

    int n0  = grp * 16 + warp * 2;
    int qi0 = b * NN + n0;
    int qi1 = qi0 + 1;
    float qx0 = qxyz[qi0 * 3 + 0], qy0 = qxyz[qi0 * 3 + 1], qz0 = qxyz[qi0 * 3 + 2];
    float qx1 = qxyz[qi1 * 3 + 0], qy1 = qxyz[qi1 * 3 + 1], qz1 = qxyz[qi1 * 3 + 2];

    float bd0 = INFINITY, bd1 = INFINITY;
    int   bi0 = 0, bi1 = 0;
    float thr0 = INFINITY, thr1 = INFINITY;
    int   cnt0 = 0, cnt1 = 0;

    for (int ch = 0; ch < MM / 32; ++ch) {
        int m = ch * 32 + lane;
        float px = sx[m], py = sy[m], pz = sz[m];
        float dx0 = qx0 - px, dy0 = qy0 - py, dz0 = qz0 - pz;
        float dx1 = qx1 - px, dy1 = qy1 - py, dz1 = qz1 - pz;
        float d20 = fmaf(dx0, dx0, fmaf(dy0, dy0, dz0 * dz0));
        float d21 = fmaf(dx1, dx1, fmaf(dy1, dy1, dz1 * dz1));

        bool pass0 = d20 < thr0;
        unsigned mask0 = __ballot_sync(0xffffffffu, pass0);
        if (mask0) {
            int pos = cnt0 + __popc(mask0 & ((1u << lane) - 1u));
            if (pass0) { bD0[pos] = d20; bI0[pos] = m; }
            cnt0 += __popc(mask0);
            if (cnt0 >= 32) knn_flush(bD0, bI0, bd0, bi0, thr0, cnt0, lane);
        }
        bool pass1 = d21 < thr1;
        unsigned mask1 = __ballot_sync(0xffffffffu, pass1);
        if (mask1) {
            int pos = cnt1 + __popc(mask1 & ((1u << lane) - 1u));
            if (pass1) { bD1[pos] = d21; bI1[pos] = m; }
            cnt1 += __popc(mask1);
            if (cnt1 >= 32) knn_flush(bD1, bI1, bd1, bi1, thr1, cnt1, lane);
        }
    }
    // tails
    if (cnt0 > 0) {
        __syncwarp();
        float nd = (lane < cnt0) ? bD0[lane] : INFINITY;
        int   ni = (lane < cnt0) ? bI0[lane] : 0;
        bsort32(nd, ni, lane);
        float rd = __shfl_sync(0xffffffffu, nd, 31 ^ lane);
        int   ri = __shfl_sync(0xffffffffu, ni, 31 ^ lane);
        if (rd < bd0) { bd0 = rd; bi0 = ri; }
        bmerge32(bd0, bi0, lane);
    }
    if (cnt1 > 0) {
        __syncwarp();
        float nd = (lane < cnt1) ? bD1[lane] : INFINITY;
        int   ni = (lane < cnt1) ? bI1[lane] : 0;
        bsort32(nd, ni, lane);
        float rd = __shfl_sync(0xffffffffu, nd, 31 ^ lane);
        int   ri = __shfl_sync(0xffffffffu, ni, 31 ^ lane);
        if (rd < bd1) { bd1 = rd; bi1 = ri; }
        bmerge32(bd1, bi1, lane);
    }
    g_idx[qi0 * KK + lane] = bi0;
    g_idx[qi1 * KK + lane] = bi1;
    unsigned nb0 = __ballot_sync(0xffffffffu, bd0 <= RAD2);
    unsigned nb1 = __ballot_sync(0xffffffffu, bd1 <= RAD2);
    if (lane == 0) {
        g_nbr[qi0] = nb0; g_idxnn[qi0] = bi0;
        g_nbr[qi1] = nb1; g_idxnn[qi1] = bi1;
    }
}

// ---------------- kernel 2a: Wgeff = Wg2@Wg1; WalT transpose ----------------
__global__ void k_compose1(const float* __restrict__ Wg1,
                           const float* __restrict__ Wg2,
                           const float* __restrict__ Wal) {
    int e = blockIdx.x * 256 + threadIdx.x;
    int o = e >> 6, i = e & 63;
    float a = 0.f;
    for (int c = 0; c < 64; ++c)
        a = fmaf(Wg2[o * 64 + c], Wg1[c * 64 + i], a);
    g_Wgeff[e] = a;
    g_WalT[i * 64 + o] = Wal[e];
}

// ---------------- kernel 2b: WqiT/WqjT; bconst ----------
__global__ void k_compose2(const float* __restrict__ Wphi,
                           const float* __restrict__ Wpsi,
                           const float* __restrict__ bphi,
                           const float* __restrict__ bpsi,
                           const float* __restrict__ bg1,
                           const float* __restrict__ bg2,
                           const float* __restrict__ Wg2) {
    int e = blockIdx.x * 256 + threadIdx.x;
    int o = e >> 6, i = e & 63;
    float qi = 0.f, qj = 0.f;
    for (int c = 0; c < 64; ++c) {
        float g = g_Wgeff[o * 64 + c];
        qi = fmaf(g, Wphi[c * 64 + i], qi);
        qj = fmaf(g, Wpsi[c * 64 + i], qj);
    }
    g_WqiT[i * 64 + o] = qi;
    g_WqjT[i * 64 + o] = qj;
    if (e < 64) {
        float a = bg2[e];
        for (int c = 0; c < 64; ++c)
            a = fmaf(Wg2[e * 64 + c], bg1[c], a);
        for (int j = 0; j < 64; ++j)
            a = fmaf(g_Wgeff[e * 64 + j], bphi[j] - bpsi[j], a);
        g_bconst[e] = a;
    }
}

// ---------------- kernel 3: per-support precompute (128 thr, 64 pts/block) ----
#define STRD 36
#define KSTR 68
constexpr int PRE_WQI = 0, PRE_WQJ = 4096, PRE_WAL = 8192, PRE_X = 12288;
constexpr int PRE_SM = PRE_X + 64 * KSTR;   // 16640 floats = 66560 B

__global__ __launch_bounds__(128) void k_pre(const float* __restrict__ feat,
                                             const float* __restrict__ bal) {
    extern __shared__ float s[];
    int tid = threadIdx.x;

    for (int i = tid; i < 4096; i += 128) {
        s[PRE_WQI + i] = g_WqiT[i];
        s[PRE_WQJ + i] = g_WqjT[i];
        s[PRE_WAL + i] = g_WalT[i];
    }

    int base = blockIdx.x * 64;               // 256 blocks, 64 points each
    int b    = base >> 12;
    int m0   = base & (MM - 1);
    float* xS = s + PRE_X;
    for (int i = tid; i < 4096; i += 128) {
        int k = i & 63, cc = i >> 6;
        xS[cc * KSTR + k] = feat[((long)b * CCH + cc) * MM + m0 + k];
    }
    __syncthreads();

    int cq = tid >> 3;            // 0..15
    int g  = tid & 7;             // 0..7 (8 k-groups of 8 over 64 points)
    int c0 = cq * 4;
    int k0 = g * 8;

    float4 aqi[8], aqj[8], aaf[8];
#pragma unroll
    for (int kk = 0; kk < 8; ++kk) {
        aqi[kk] = make_float4(0.f, 0.f, 0.f, 0.f);
        aqj[kk] = make_float4(0.f, 0.f, 0.f, 0.f);
        aaf[kk] = make_float4(0.f, 0.f, 0.f, 0.f);
    }
    {
        const float* Wi = s + PRE_WQI + c0;
        const float* Wj = s + PRE_WQJ + c0;
        const float* Wa = s + PRE_WAL + c0;
        const float* xb = xS + k0;
#pragma unroll 4
        for (int c2 = 0; c2 < 64; ++c2) {
            float4 wi4 = *(const float4*)(Wi + c2 * 64);
            float4 wj4 = *(const float4*)(Wj + c2 * 64);
            float4 wa4 = *(const float4*)(Wa + c2 * 64);
            float4 x0 = *(const float4*)(xb + c2 * KSTR);
            float4 x1 = *(const float4*)(xb + c2 * KSTR + 4);
#pragma unroll
            for (int kk = 0; kk < 8; ++kk) {
                float xv = (kk < 4) ? (&x0.x)[kk] : (&x1.x)[kk - 4];
                aqi[kk].x = fmaf(wi4.x, xv, aqi[kk].x);
                aqi[kk].y = fmaf(wi4.y, xv, aqi[kk].y);
                aqi[kk].z = fmaf(wi4.z, xv, aqi[kk].z);
                aqi[kk].w = fmaf(wi4.w, xv, aqi[kk].w);
                aqj[kk].x = fmaf(wj4.x, xv, aqj[kk].x);
                aqj[kk].y = fmaf(wj4.y, xv, aqj[kk].y);
                aqj[kk].z = fmaf(wj4.z, xv, aqj[kk].z);
                aqj[kk].w = fmaf(wj4.w, xv, aqj[kk].w);
                aaf[kk].x = fmaf(wa4.x, xv, aaf[kk].x);
                aaf[kk].y = fmaf(wa4.y, xv, aaf[kk].y);
                aaf[kk].z = fmaf(wa4.z, xv, aaf[kk].z);
                aaf[kk].w = fmaf(wa4.w, xv, aaf[kk].w);
            }
        }
    }
    float4 balv = *(const float4*)(bal + c0);
#pragma unroll
    for (int kk = 0; kk < 8; ++kk) {
        long o = (long)(base + k0 + kk) * 64 + c0;
        *(float4*)(g_Qi + o) = aqi[kk];
        *(float4*)(g_Qj + o) = aqj[kk];
        float4 af = aaf[kk];
        af.x += balv.x; af.y += balv.y; af.z += balv.z; af.w += balv.w;
        *(float4*)(g_AF + o) = af;
    }
}

// ---------------- kernel 4: fused per-query (R12, proven) ----------------
struct P2 {
    const float *qxyz, *sxyz;
    const int   *qmask;
    const float *Wth1, *bth1, *Wth2, *bth2;
    const float *gt, *bet, *rmt, *rvt, *gg, *beg, *rmg, *rvg;
    float* out;
};

constexpr int OFF_WG   = 0;
constexpr int OFF_WEFF = 4096;
constexpr int OFF_CC   = 4352;
constexpr int OFF_BN   = 4416;
constexpr int OFF_Q    = 4672;
constexpr int QO_DL = 0, QO_POS = 2304, QO_FM = 2432, QO_KIDX = 2464;
constexpr int QSZ = 2496;
constexpr int SMEM_FLOATS = OFF_Q + 4 * QSZ;

__global__ __launch_bounds__(128, 2) void k_main(P2 p) {
    extern __shared__ float sm[];
    int tid = threadIdx.x;

    {
        for (int i = tid; i < 4096; i += 128) {
            int o = i >> 6, in = i & 63;
            sm[OFF_WG + in * 64 + o] = g_Wgeff[i];
        }
        for (int i = tid; i < 256; i += 128) {
            int cc = i >> 2, j = i & 3;
            float acc;
            if (j < 3) {
                acc = 0.f;
                for (int c2 = 0; c2 < 64; ++c2)
                    acc = fmaf(p.Wth2[cc * 64 + c2], p.Wth1[c2 * 3 + j], acc);
            } else {
                acc = p.bth2[cc];
                for (int c2 = 0; c2 < 64; ++c2)
                    acc = fmaf(p.Wth2[cc * 64 + c2], p.bth1[c2], acc);
            }
            sm[OFF_WEFF + cc * 4 + j] = acc;
        }
        if (tid < 64) {
            int i = tid;
            sm[OFF_CC + i] = g_bconst[i];
            float it = p.gt[i] * rsqrtf(p.rvt[i] + EPSV);
            sm[OFF_BN + 0 * 64 + i] = it;
            sm[OFF_BN + 1 * 64 + i] = p.bet[i] - p.rmt[i] * it;
            float ig = p.gg[i] * rsqrtf(p.rvg[i] + EPSV);
            sm[OFF_BN + 2 * 64 + i] = ig;
            sm[OFF_BN + 3 * 64 + i] = p.beg[i] - p.rmg[i] * ig;
        }
    }
    __syncthreads();

    int pr = tid >> 6;
    int t  = tid & 63;
    int g  = t & 7;
    int cq = t >> 3;
    int c0 = cq * 8;
    int k0 = g * 4;

    float* QA = sm + OFF_Q + (pr * 2 + 0) * QSZ;
    float* QB = sm + OFF_Q + (pr * 2 + 1) * QSZ;

    const int ngrp = (BB * NN) / 4;
    for (int grp = blockIdx.x; grp < ngrp; grp += gridDim.x) {
        int b  = (grp * 4) >> 12;
        long rowbase = (long)b * MM;

        {
            int qq = tid >> 5;
            int k  = tid & 31;
            int qi = grp * 4 + qq;
            float* Q = sm + OFF_Q + qq * QSZ;
            int ki = g_idx[qi * KK + k];
            ((int*)(Q + QO_KIDX))[k] = ki;
            float qx = p.qxyz[qi * 3 + 0];
            float qy = p.qxyz[qi * 3 + 1];
            float qz = p.qxyz[qi * 3 + 2];
            const float* s = p.sxyz + (rowbase + ki) * 3;
            float4 pp;
            pp.x = (s[0] - qx) * (1.0f / RADIUS);
            pp.y = (s[1] - qy) * (1.0f / RADIUS);
            pp.z = (s[2] - qz) * (1.0f / RADIUS);
            pp.w = 0.f;
            *(float4*)(Q + QO_POS + k * 4) = pp;
            unsigned nb = g_nbr[qi];
            int qm = p.qmask[qi];
            (Q + QO_FM)[k] = (float)((nb >> k) & 1u) + (1.0f - (float)qm);
        }
        __syncthreads();   // S1

        {
            float4 invtL = *(const float4*)(sm + OFF_BN + 0 * 64 + c0);
            float4 invtH = *(const float4*)(sm + OFF_BN + 0 * 64 + c0 + 4);
            float4 shtL  = *(const float4*)(sm + OFF_BN + 1 * 64 + c0);
            float4 shtH  = *(const float4*)(sm + OFF_BN + 1 * 64 + c0 + 4);
            float4 pA[4], pB[4];
#pragma unroll
            for (int kk = 0; kk < 4; ++kk) {
                pA[kk] = *(const float4*)(QA + QO_POS + (k0 + kk) * 4);
                pB[kk] = *(const float4*)(QB + QO_POS + (k0 + kk) * 4);
            }
#pragma unroll
            for (int j = 0; j < 8; ++j) {
                float4 wej = *(const float4*)(sm + OFF_WEFF + (c0 + j) * 4);
                float it = (j < 4) ? (&invtL.x)[j] : (&invtH.x)[j - 4];
                float sh = (j < 4) ? (&shtL.x)[j] : (&shtH.x)[j - 4];
                float4 rA, rB;
#pragma unroll
                for (int kk = 0; kk < 4; ++kk) {
                    float dA = wej.w, dB = wej.w;
                    dA = fmaf(wej.x, pA[kk].x, dA); dB = fmaf(wej.x, pB[kk].x, dB);
                    dA = fmaf(wej.y, pA[kk].y, dA); dB = fmaf(wej.y, pB[kk].y, dB);
                    dA = fmaf(wej.z, pA[kk].z, dA); dB = fmaf(wej.z, pB[kk].z, dB);
                    (&rA.x)[kk] = fmaxf(fmaf(dA, it, sh), 0.f);
                    (&rB.x)[kk] = fmaxf(fmaf(dB, it, sh), 0.f);
                }
                *(float4*)(QA + QO_DL + (c0 + j) * STRD + k0) = rA;
                *(float4*)(QB + QO_DL + (c0 + j) * STRD + k0) = rB;
            }
        }
        __syncthreads();   // S2

        float accA[32], accB[32];
#pragma unroll
        for (int i = 0; i < 32; ++i) { accA[i] = 0.f; accB[i] = 0.f; }
        {
            const float* W  = sm + OFF_WG + c0;
            const float* dA = QA + QO_DL + k0;
            const float* dB = QB + QO_DL + k0;
#pragma unroll 2
            for (int c2 = 0; c2 < 64; ++c2) {
                float4 w0 = *(const float4*)(W + c2 * 64);
                float4 w1 = *(const float4*)(W + c2 * 64 + 4);
                float4 a4 = *(const float4*)(dA + c2 * STRD);
                float4 b4 = *(const float4*)(dB + c2 * STRD);
#pragma unroll
                for (int j = 0; j < 8; ++j) {
                    float w = (j < 4) ? (&w0.x)[j] : (&w1.x)[j - 4];
                    accA[j * 4 + 0] = fmaf(w, a4.x, accA[j * 4 + 0]);
                    accA[j * 4 + 1] = fmaf(w, a4.y, accA[j * 4 + 1]);
                    accA[j * 4 + 2] = fmaf(w, a4.z, accA[j * 4 + 2]);
                    accA[j * 4 + 3] = fmaf(w, a4.w, accA[j * 4 + 3]);
                    accB[j * 4 + 0] = fmaf(w, b4.x, accB[j * 4 + 0]);
                    accB[j * 4 + 1] = fmaf(w, b4.y, accB[j * 4 + 1]);
                    accB[j * 4 + 2] = fmaf(w, b4.z, accB[j * 4 + 2]);
                    accB[j * 4 + 3] = fmaf(w, b4.w, accB[j * 4 + 3]);
                }
            }
        }

        float4 bcnL  = *(const float4*)(sm + OFF_CC + c0);
        float4 bcnH  = *(const float4*)(sm + OFF_CC + c0 + 4);
        float4 invgL = *(const float4*)(sm + OFF_BN + 2 * 64 + c0);
        float4 invgH = *(const float4*)(sm + OFF_BN + 2 * 64 + c0 + 4);
        float4 shgL  = *(const float4*)(sm + OFF_BN + 3 * 64 + c0);
        float4 shgH  = *(const float4*)(sm + OFF_BN + 3 * 64 + c0 + 4);
#pragma unroll
        for (int qq = 0; qq < 2; ++qq) {
            int qi = grp * 4 + pr * 2 + qq;
            int n  = qi & (NN - 1);
            float* Q = qq ? QB : QA;
            float* acc = qq ? accB : accA;
            int* kidx = (int*)(Q + QO_KIDX);
            float* fmB = Q + QO_FM;

            float4 dl4[8];
#pragma unroll
            for (int j = 0; j < 8; ++j)
                dl4[j] = *(const float4*)(Q + QO_DL + (c0 + j) * STRD + k0);

            int nn = g_idxnn[qi];
            float4 qiL = *(const float4*)(g_Qi + (rowbase + nn) * 64 + c0);
            float4 qiH = *(const float4*)(g_Qi + (rowbase + nn) * 64 + c0 + 4);
            float se[8] = {0.f, 0.f, 0.f, 0.f, 0.f, 0.f, 0.f, 0.f};
            float sf[8] = {0.f, 0.f, 0.f, 0.f, 0.f, 0.f, 0.f, 0.f};
#pragma unroll
            for (int kk = 0; kk < 4; ++kk) {
                int k = k0 + kk;
                int ridx = kidx[k];
                float4 qjL = *(const float4*)(g_Qj + (rowbase + ridx) * 64 + c0);
                float4 qjH = *(const float4*)(g_Qj + (rowbase + ridx) * 64 + c0 + 4);
                float4 afL = *(const float4*)(g_AF + (rowbase + ridx) * 64 + c0);
                float4 afH = *(const float4*)(g_AF + (rowbase + ridx) * 64 + c0 + 4);
                float fm = fmB[k];
#pragma unroll
                for (int j = 0; j < 8; ++j) {
                    float qiv = (j < 4) ? (&qiL.x)[j] : (&qiH.x)[j - 4];
                    float qjv = (j < 4) ? (&qjL.x)[j] : (&qjH.x)[j - 4];
                    float afv = (j < 4) ? (&afL.x)[j] : (&afH.x)[j - 4];
                    float bc  = (j < 4) ? (&bcnL.x)[j] : (&bcnH.x)[j - 4];
                    float ig  = (j < 4) ? (&invgL.x)[j] : (&invgH.x)[j - 4];
                    float sg  = (j < 4) ? (&shgL.x)[j] : (&shgH.x)[j - 4];
                    float pre2 = qiv - qjv + acc[j * 4 + kk] + bc;
                    float v = fmaxf(fmaf(pre2, ig, sg), 0.f);
                    float e = __expf(v);
                    float ftv = (afv + (&dl4[j].x)[kk]) * fm;
                    se[j] += e;
                    sf[j] = fmaf(e, ftv, sf[j]);
                }
            }
#pragma unroll
            for (int j = 0; j < 8; ++j) {
                float s1 = se[j], s2 = sf[j];
                s1 += __shfl_xor_sync(0xffffffffu, s1, 1);
                s2 += __shfl_xor_sync(0xffffffffu, s2, 1);
                s1 += __shfl_xor_sync(0xffffffffu, s1, 2);
                s2 += __shfl_xor_sync(0xffffffffu, s2, 2);
                s1 += __shfl_xor_sync(0xffffffffu, s1, 4);
                s2 += __shfl_xor_sync(0xffffffffu, s2, 4);
                if (g == 0)
                    p.out[((long)b * CCH + c0 + j) * NN + n] = s2 / s1;
            }
        }
        __syncthreads();   // S3
    }
}

// ---------------- host launcher ----------------
extern "C" void kernel_launch(void* const* d_in, const int* in_sizes, int n_in,
                              void* d_out, int out_size) {
    const float* qxyz  = (const float*)d_in[0];
    const float* sxyz  = (const float*)d_in[1];
    const int*   qmask = (const int*)d_in[2];
    const int*   smask = (const int*)d_in[3];
    const float* feat  = (const float*)d_in[4];
    const float* Wth1  = (const float*)d_in[5];
    const float* bth1  = (const float*)d_in[6];
    const float* Wth2  = (const float*)d_in[7];
    const float* bth2  = (const float*)d_in[8];
    const float* Wphi  = (const float*)d_in[9];
    const float* bphi  = (const float*)d_in[10];
    const float* Wpsi  = (const float*)d_in[11];
    const float* bpsi  = (const float*)d_in[12];
    const float* Wal   = (const float*)d_in[13];
    const float* bal   = (const float*)d_in[14];
    const float* Wg1   = (const float*)d_in[15];
    const float* bg1   = (const float*)d_in[16];
    const float* Wg2   = (const float*)d_in[17];
    const float* bg2   = (const float*)d_in[18];

    P2 p;
    p.qxyz = qxyz; p.sxyz = sxyz; p.qmask = qmask;
    p.Wth1 = Wth1; p.bth1 = bth1; p.Wth2 = Wth2; p.bth2 = bth2;
    p.gt   = (const float*)d_in[19]; p.bet  = (const float*)d_in[20];
    p.rmt  = (const float*)d_in[21]; p.rvt  = (const float*)d_in[22];
    p.gg   = (const float*)d_in[23]; p.beg  = (const float*)d_in[24];
    p.rmg  = (const float*)d_in[25]; p.rvg  = (const float*)d_in[26];
    p.out  = (float*)d_out;

    k_compose1<<<16, 256>>>(Wg1, Wg2, Wal);
    k_compose2<<<16, 256>>>(Wphi, Wpsi, bphi, bpsi, bg1, bg2, Wg2);

    cudaFuncSetAttribute(k_knn, cudaFuncAttributeMaxDynamicSharedMemorySize,
                         KNN_SM_FLOATS * 4);
    k_knn<<<(BB * NN) / 16, 256, KNN_SM_FLOATS * 4>>>(qxyz, sxyz, smask);

    cudaFuncSetAttribute(k_pre, cudaFuncAttributeMaxDynamicSharedMemorySize,
                         PRE_SM * 4);
    k_pre<<<(BB * MM) / 64, 128, PRE_SM * 4>>>(feat, bal);

    cudaFuncSetAttribute(k_main, cudaFuncAttributeMaxDynamicSharedMemorySize,
                         SMEM_FLOATS * 4);
    int dev = 0, nsm = 148;
    cudaGetDevice(&dev);
    cudaDeviceGetAttribute(&nsm, cudaDevAttrMultiProcessorCount, dev);
    k_main<<<2 * nsm, 128, SMEM_FLOATS * 4>>>(p);
}